// round 13
// baseline (speedup 1.0000x reference)
#include <cuda_runtime.h>
#include <cuda_bf16.h>
#include <cuda_fp16.h>
#include <math.h>

#define NB   2
#define TT   4096
#define HIDD 1024
#define NHH  16
#define DD   64
#define TOPKK 16
#define NEGV (-10000.0f)

// ---------------- device scratch ----------------
__device__ float g_q[(size_t)NB*NHH*TT*DD];     // tf32-rounded (attn only)
__device__ float g_k[(size_t)NB*NHH*TT*DD];     // exact (selection, bos)
__device__ float g_ktf[(size_t)NB*NHH*TT*DD];   // tf32-rounded (attn)
__device__ float g_v[(size_t)NB*NHH*TT*DD];     // tf32-rounded (attn, bos)
__device__ float g_q0[(size_t)NB*HIDD];
__device__ int   g_gidx[(size_t)NB*NHH*(TT/4)];
__device__ int   g_lidx[(size_t)NB*NHH*(3*TT/4)];
__device__ uint4 g_Afh4[(size_t)NB*TT*HIDD/8];
__device__ uint4 g_Afl4[(size_t)NB*TT*HIDD/8];
__device__ uint4 g_Wfh4[(size_t)3*HIDD*HIDD/8];  // 0=Wq, 1=Wv, 2=Wk
__device__ uint4 g_Wfl4[(size_t)HIDD*HIDD/8];    // Wk lo

// ---------------- helpers ----------------
// NOTE: non-volatile on purpose — pure register math, lets ptxas schedule
__device__ __forceinline__ void mma_f16(float& d0, float& d1, float& d2, float& d3,
                                        unsigned a0, unsigned a1, unsigned a2, unsigned a3,
                                        unsigned b0, unsigned b1)
{
    asm("mma.sync.aligned.m16n8k16.row.col.f32.f16.f16.f32 "
        "{%0,%1,%2,%3}, {%4,%5,%6,%7}, {%8,%9}, {%0,%1,%2,%3};\n"
        : "+f"(d0), "+f"(d1), "+f"(d2), "+f"(d3)
        : "r"(a0), "r"(a1), "r"(a2), "r"(a3), "r"(b0), "r"(b1));
}

__device__ __forceinline__ void ldsm4(unsigned& r0, unsigned& r1,
                                      unsigned& r2, unsigned& r3, unsigned saddr)
{
    asm volatile("ldmatrix.sync.aligned.m8n8.x4.shared.b16 {%0,%1,%2,%3}, [%4];"
                 : "=r"(r0), "=r"(r1), "=r"(r2), "=r"(r3) : "r"(saddr));
}

__device__ __forceinline__ void cp16(void* smem_dst, const void* gsrc)
{
    unsigned saddr = (unsigned)__cvta_generic_to_shared(smem_dst);
    asm volatile("cp.async.ca.shared.global [%0], [%1], 16;\n"
                 :: "r"(saddr), "l"(gsrc));
}
__device__ __forceinline__ void cp_commit()
{
    asm volatile("cp.async.commit_group;\n" ::: "memory");
}
template <int N> __device__ __forceinline__ void cp_wait()
{
    asm volatile("cp.async.wait_group %0;\n" :: "n"(N) : "memory");
}

__device__ __forceinline__ float to_tf32(float x)
{
    float r;
    asm("cvt.rna.tf32.f32 %0, %1;" : "=f"(r) : "f"(x));
    return r;
}

__device__ __forceinline__ void mma_tf32(float& d0, float& d1, float& d2, float& d3,
                                         float a0, float a1, float a2, float a3,
                                         float b0, float b1)
{
    asm("mma.sync.aligned.m16n8k8.row.col.f32.tf32.tf32.f32 "
        "{%0,%1,%2,%3}, {%4,%5,%6,%7}, {%8,%9}, {%0,%1,%2,%3};\n"
        : "+f"(d0), "+f"(d1), "+f"(d2), "+f"(d3)
        : "r"(__float_as_uint(a0)), "r"(__float_as_uint(a1)),
          "r"(__float_as_uint(a2)), "r"(__float_as_uint(a3)),
          "r"(__float_as_uint(b0)), "r"(__float_as_uint(b1)));
}

// ---------------- conversions ------------------------------------------------------
__device__ __forceinline__ uint2 pack_hi4(float4 v)
{
    __half h0 = __float2half_rn(v.x), h1 = __float2half_rn(v.y);
    __half h2 = __float2half_rn(v.z), h3 = __float2half_rn(v.w);
    return make_uint2((unsigned)__half_as_ushort(h0) | ((unsigned)__half_as_ushort(h1) << 16),
                      (unsigned)__half_as_ushort(h2) | ((unsigned)__half_as_ushort(h3) << 16));
}
__device__ __forceinline__ uint2 pack_lo4(float4 v)
{
    __half h0 = __float2half_rn(v.x), h1 = __float2half_rn(v.y);
    __half h2 = __float2half_rn(v.z), h3 = __float2half_rn(v.w);
    __half l0 = __float2half_rn(v.x - __half2float(h0));
    __half l1 = __float2half_rn(v.y - __half2float(h1));
    __half l2 = __float2half_rn(v.z - __half2float(h2));
    __half l3 = __float2half_rn(v.w - __half2float(h3));
    return make_uint2((unsigned)__half_as_ushort(l0) | ((unsigned)__half_as_ushort(l1) << 16),
                      (unsigned)__half_as_ushort(l2) | ((unsigned)__half_as_ushort(l3) << 16));
}

__global__ void cvt_a_kernel(const float* __restrict__ in,
                             uint2* __restrict__ fh, uint2* __restrict__ fl, int n4)
{
    int i = blockIdx.x * blockDim.x + threadIdx.x;
    if (i >= n4) return;
    float4 v = ((const float4*)in)[i];
    fh[i] = pack_hi4(v);
    fl[i] = pack_lo4(v);
}

__global__ void cvt_w_kernel(const float* __restrict__ Wq,
                             const float* __restrict__ Wk,
                             const float* __restrict__ Wv,
                             uint2* __restrict__ fh, uint2* __restrict__ fl, int n4)
{
    int i = blockIdx.x * blockDim.x + threadIdx.x;
    if (i >= n4) return;
    int w = blockIdx.y;
    const float* in = (w == 0) ? Wq : (w == 1) ? Wk : Wv;
    int slot = (w == 0) ? 0 : (w == 1) ? 2 : 1;
    float4 v = ((const float4*)in)[i];
    fh[(size_t)slot * n4 + i] = pack_hi4(v);
    if (w == 1) fl[i] = pack_lo4(v);
}

__global__ void q0_kernel(const float* __restrict__ hs,
                          const float* __restrict__ Wq,
                          const float* __restrict__ bq)
{
    const int c = blockIdx.x;
    const int n = blockIdx.y;
    const int tid = threadIdx.x;
    __shared__ float red[128];
    const float* xr = hs + (size_t)n * TT * HIDD;
    const float* wr = Wq + (size_t)c * HIDD;
    float pa = 0.0f;
    for (int k = tid; k < HIDD; k += 128) pa = fmaf(xr[k], wr[k], pa);
    red[tid] = pa;
    __syncthreads();
    for (int off = 64; off > 0; off >>= 1) {
        if (tid < off) red[tid] += red[tid + off];
        __syncthreads();
    }
    if (tid == 0) g_q0[(size_t)n * HIDD + c] = red[0] + bq[c];
}

// ============= fused QKV GEMM: term-major MMA scheduling ==========================
#define KSTR 16
#define PLW  (128 * KSTR)
#define PA_HI 0
#define PA_LO (1 * PLW)
#define PB_HI (2 * PLW)
#define PB_LO (3 * PLW)
#define STGW  (4 * PLW)
#define GSMEMB (3 * STGW * 4)          /* 96KB */

__global__ __launch_bounds__(256, 2)
void gemm_all_kernel(const float* __restrict__ bq,
                     const float* __restrict__ bk,
                     const float* __restrict__ bv,
                     float* __restrict__ oq,
                     float* __restrict__ ok,
                     float* __restrict__ oktf,
                     float* __restrict__ ov)
{
    extern __shared__ unsigned gsm[];
    const int tid = threadIdx.x;
    const int m0 = blockIdx.y * 128;
    const int n0 = blockIdx.x * 128;
    const int z  = blockIdx.z;
    const bool isK = (z == 2);

    const char* Ah = (const char*)((const __half*)g_Afh4 + (size_t)m0 * HIDD);
    const char* Al = (const char*)((const __half*)g_Afl4 + (size_t)m0 * HIDD);
    const char* Bh = (const char*)((const __half*)g_Wfh4 + ((size_t)z * HIDD + n0) * HIDD);
    const char* Bl = (const char*)((const __half*)g_Wfl4 + (size_t)n0 * HIDD);
    const float* bias = (z == 0) ? bq : (z == 1) ? bv : bk;

    const int lane = tid & 31;
    const int warp = tid >> 5;
    const int wm = warp >> 1;
    const int wn = warp & 1;
    const int qr = lane >> 2;
    const int qc = lane & 3;
    const int rA = wm * 32;
    const int cB = wn * 64;

    const unsigned smem_base = (unsigned)__cvta_generic_to_shared(gsm);
    const int a_r0 = rA + (lane & 7) + ((lane >> 3) & 1) * 8;
    const unsigned a_kbit = (lane >> 4) & 1;
    const int b_r0 = cB + (lane & 7) + ((lane >> 4) & 1) * 8;
    const unsigned b_kbit = (lane >> 3) & 1;

    float acc[2][8][4];
#pragma unroll
    for (int mt = 0; mt < 2; mt++)
#pragma unroll
        for (int nt = 0; nt < 8; nt++)
#pragma unroll
            for (int e = 0; e < 4; e++) acc[mt][nt][e] = 0.0f;

    auto load_stage = [&](int buf, int kofs) {
        unsigned* st = gsm + buf * STGW;
#pragma unroll
        for (int i = 0; i < 2; i++) {
            int c = tid + i * 256;
            int row = c >> 2;
            int cw = c & 3;
            size_t go = ((size_t)row * HIDD + kofs + cw * 8) * 2;
            int pw = (cw ^ ((row >> 1) & 3)) * 4;
            unsigned* sp = st + row * KSTR + pw;
            cp16(sp + PA_HI, Ah + go);
            cp16(sp + PA_LO, Al + go);
            cp16(sp + PB_HI, Bh + go);
            if (isK) cp16(sp + PB_LO, Bl + go);
        }
        cp_commit();
    };

    load_stage(0, 0);
    load_stage(1, 32);

    const int NIT = HIDD / 32;
    int cur = 0;
    for (int it = 0; it < NIT; it++) {
        if (it + 1 < NIT) cp_wait<1>(); else cp_wait<0>();
        __syncthreads();
        if (it + 2 < NIT) {
            int s2 = cur + 2; if (s2 >= 3) s2 -= 3;
            load_stage(s2, (it + 2) * 32);
        }

        const unsigned sb = smem_base + cur * (STGW * 4);
#pragma unroll
        for (int s = 0; s < 2; s++) {
            unsigned a_hi[2][4], a_lo[2][4];
#pragma unroll
            for (int mt = 0; mt < 2; mt++) {
                int row = a_r0 + mt * 16;
                unsigned kc = (unsigned)s * 2 + a_kbit;
                unsigned ao = (unsigned)row * 64 + ((kc ^ ((unsigned)(row >> 1) & 3u)) << 4);
                ldsm4(a_hi[mt][0], a_hi[mt][1], a_hi[mt][2], a_hi[mt][3],
                      sb + PA_HI * 4 + ao);
                ldsm4(a_lo[mt][0], a_lo[mt][1], a_lo[mt][2], a_lo[mt][3],
                      sb + PA_LO * 4 + ao);
            }
            // process p in pairs; term-major inside the pair (chain distance 8)
#pragma unroll
            for (int ph = 0; ph < 2; ph++) {
                unsigned bh[2][4], bl[2][4];
#pragma unroll
                for (int pp = 0; pp < 2; pp++) {
                    int p = ph * 2 + pp;
                    int row = b_r0 + p * 16;
                    unsigned kc = (unsigned)s * 2 + b_kbit;
                    unsigned bo = (unsigned)row * 64 + ((kc ^ ((unsigned)(row >> 1) & 3u)) << 4);
                    ldsm4(bh[pp][0], bh[pp][1], bh[pp][2], bh[pp][3],
                          sb + PB_HI * 4 + bo);
                    if (isK)
                        ldsm4(bl[pp][0], bl[pp][1], bl[pp][2], bl[pp][3],
                              sb + PB_LO * 4 + bo);
                }
                // term 1: hi*hi (8 independent MMAs)
#pragma unroll
                for (int pp = 0; pp < 2; pp++) {
                    int p = ph * 2 + pp;
#pragma unroll
                    for (int mt = 0; mt < 2; mt++) {
                        float* c0 = acc[mt][2 * p];
                        float* c1 = acc[mt][2 * p + 1];
                        mma_f16(c0[0], c0[1], c0[2], c0[3],
                                a_hi[mt][0], a_hi[mt][1], a_hi[mt][2], a_hi[mt][3],
                                bh[pp][0], bh[pp][1]);
                        mma_f16(c1[0], c1[1], c1[2], c1[3],
                                a_hi[mt][0], a_hi[mt][1], a_hi[mt][2], a_hi[mt][3],
                                bh[pp][2], bh[pp][3]);
                    }
                }
                // term 2: lo*hi
#pragma unroll
                for (int pp = 0; pp < 2; pp++) {
                    int p = ph * 2 + pp;
#pragma unroll
                    for (int mt = 0; mt < 2; mt++) {
                        float* c0 = acc[mt][2 * p];
                        float* c1 = acc[mt][2 * p + 1];
                        mma_f16(c0[0], c0[1], c0[2], c0[3],
                                a_lo[mt][0], a_lo[mt][1], a_lo[mt][2], a_lo[mt][3],
                                bh[pp][0], bh[pp][1]);
                        mma_f16(c1[0], c1[1], c1[2], c1[3],
                                a_lo[mt][0], a_lo[mt][1], a_lo[mt][2], a_lo[mt][3],
                                bh[pp][2], bh[pp][3]);
                    }
                }
                // term 3 (K only): hi*lo
                if (isK) {
#pragma unroll
                    for (int pp = 0; pp < 2; pp++) {
                        int p = ph * 2 + pp;
#pragma unroll
                        for (int mt = 0; mt < 2; mt++) {
                            float* c0 = acc[mt][2 * p];
                            float* c1 = acc[mt][2 * p + 1];
                            mma_f16(c0[0], c0[1], c0[2], c0[3],
                                    a_hi[mt][0], a_hi[mt][1], a_hi[mt][2], a_hi[mt][3],
                                    bl[pp][0], bl[pp][1]);
                            mma_f16(c1[0], c1[1], c1[2], c1[3],
                                    a_hi[mt][0], a_hi[mt][1], a_hi[mt][2], a_hi[mt][3],
                                    bl[pp][2], bl[pp][3]);
                        }
                    }
                }
            }
        }
        cur = (cur + 1 == 3) ? 0 : cur + 1;
    }

#pragma unroll
    for (int mt = 0; mt < 2; mt++) {
#pragma unroll
        for (int nt = 0; nt < 8; nt++) {
#pragma unroll
            for (int half = 0; half < 2; half++) {
                int row = m0 + rA + mt * 16 + qr + half * 8;
                int nb  = row >> 12;
                int t   = row & (TT - 1);
                int col = n0 + cB + nt * 8 + qc * 2;
                int h = col >> 6;
                int d = col & 63;
                size_t off = (((size_t)(nb * NHH + h)) * TT + t) * DD + d;
                float v0 = acc[mt][nt][half * 2 + 0] + bias[col];
                float v1 = acc[mt][nt][half * 2 + 1] + bias[col + 1];
                if (isK) {
                    ok[off] = v0; ok[off + 1] = v1;
                    oktf[off] = to_tf32(v0); oktf[off + 1] = to_tf32(v1);
                } else {
                    float* op = (z == 0) ? oq : ov;
                    op[off] = to_tf32(v0); op[off + 1] = to_tf32(v1);
                }
            }
        }
    }
}

// ---------------- top-k selection (exact g_k) -------------------------------------
__global__ void select_kernel(const float* __restrict__ mask,
                              const float* __restrict__ bq)
{
    const int sub = threadIdx.x >> 6;
    const int i   = threadIdx.x & 63;
    const int blk = blockIdx.x * 4 + sub;
    const int h   = blockIdx.y;
    const int n   = blockIdx.z;
    __shared__ float norms[4][64];
    __shared__ int flags[4][64];

    const int token = blk * 64 + i;
    const float* kr = g_k + (((size_t)(n * NHH + h)) * TT + token) * DD;
    const float* bqr = bq + h * DD;
    float s = 0.0f;
#pragma unroll
    for (int d = 0; d < DD; d++) { float vv = kr[d] + bqr[d]; s += vv * vv; }
    if (mask[n * TT + token] != 0.0f) s = 0.0f;
    norms[sub][i] = s;
    __syncthreads();

    float mine = norms[sub][i];
    int rank = 0;
    for (int j = 0; j < 64; j++) {
        float nj = norms[sub][j];
        rank += (nj < mine) || (nj == mine && j < i);
    }
    int top = (rank >= 64 - TOPKK) ? 1 : 0;
    flags[sub][i] = top;
    __syncthreads();

    int pos = 0;
    for (int j = 0; j < i; j++) pos += flags[sub][j];
    if (top)
        g_gidx[((size_t)(n * NHH + h)) * (TT / 4) + blk * TOPKK + pos] = token;
    else
        g_lidx[((size_t)(n * NHH + h)) * (3 * TT / 4) + blk * 48 + (i - pos)] = token;
}

// ======== fused local+global flash, cp.async-pipelined gathers ====================
#define KC     112
#define NCH    4
#define QSTRW  68
#define VSTRW  72
#define QS_OFF 0
#define KS_OFF (QS_OFF + 128*QSTRW)
#define VS_OFF (KS_OFF + KC*QSTRW)
#define MS_OFF (VS_OFF + KC*VSTRW)
#define LSMEM_WORDS (MS_OFF + KC)

template <int NT>
__device__ __forceinline__ void compute_S(
    const float* __restrict__ Qs, const float* __restrict__ Ks,
    float (&s)[14][4], int rb, int w16, int qr, int qc)
{
#pragma unroll
    for (int nt = 0; nt < NT; nt++) {
        s[nt][0] = 0.f; s[nt][1] = 0.f; s[nt][2] = 0.f; s[nt][3] = 0.f;
    }
#pragma unroll
    for (int k8 = 0; k8 < 8; k8++) {
        const int kc0 = k8 * 8 + qc;
        float a0 = Qs[(w16 + qr) * QSTRW + kc0];
        float a1 = Qs[(w16 + qr + 8) * QSTRW + kc0];
        float a2 = Qs[(w16 + qr) * QSTRW + kc0 + 4];
        float a3 = Qs[(w16 + qr + 8) * QSTRW + kc0 + 4];
#pragma unroll
        for (int nt = 0; nt < NT; nt++) {
            float b0 = Ks[(rb + nt * 8 + qr) * QSTRW + kc0];
            float b1 = Ks[(rb + nt * 8 + qr) * QSTRW + kc0 + 4];
            mma_tf32(s[nt][0], s[nt][1], s[nt][2], s[nt][3],
                     a0, a1, a2, a3, b0, b1);
        }
    }
}

template <int NT>
__device__ __forceinline__ void softmax_pv(
    const float* __restrict__ Vs, const float* __restrict__ Ms,
    float (&s)[14][4], int rb, int w16, int qr, int qc,
    int src0, int src2, bool odd,
    float& m0, float& m1, float& l0, float& l1, float (&o)[8][4])
{
    float cmax0 = -1e30f, cmax1 = -1e30f;
#pragma unroll
    for (int nt = 0; nt < NT; nt++) {
        float mc0 = Ms[rb + nt * 8 + 2 * qc];
        float mc1 = Ms[rb + nt * 8 + 2 * qc + 1];
        s[nt][0] = s[nt][0] * 0.125f + mc0;
        s[nt][1] = s[nt][1] * 0.125f + mc1;
        s[nt][2] = s[nt][2] * 0.125f + mc0;
        s[nt][3] = s[nt][3] * 0.125f + mc1;
        cmax0 = fmaxf(cmax0, fmaxf(s[nt][0], s[nt][1]));
        cmax1 = fmaxf(cmax1, fmaxf(s[nt][2], s[nt][3]));
    }
    cmax0 = fmaxf(cmax0, __shfl_xor_sync(0xffffffffu, cmax0, 1));
    cmax0 = fmaxf(cmax0, __shfl_xor_sync(0xffffffffu, cmax0, 2));
    cmax1 = fmaxf(cmax1, __shfl_xor_sync(0xffffffffu, cmax1, 1));
    cmax1 = fmaxf(cmax1, __shfl_xor_sync(0xffffffffu, cmax1, 2));

    float mn0 = fmaxf(m0, cmax0);
    float mn1 = fmaxf(m1, cmax1);
    float corr0 = __expf(m0 - mn0);
    float corr1 = __expf(m1 - mn1);
    m0 = mn0; m1 = mn1;

    float rs0 = 0.0f, rs1 = 0.0f;
#pragma unroll
    for (int nt = 0; nt < NT; nt++) {
        float p0 = __expf(s[nt][0] - mn0);
        float p1 = __expf(s[nt][1] - mn0);
        float p2 = __expf(s[nt][2] - mn1);
        float p3 = __expf(s[nt][3] - mn1);
        rs0 += p0 + p1; rs1 += p2 + p3;
        s[nt][0] = to_tf32(p0); s[nt][1] = to_tf32(p1);
        s[nt][2] = to_tf32(p2); s[nt][3] = to_tf32(p3);
    }
    rs0 += __shfl_xor_sync(0xffffffffu, rs0, 1);
    rs0 += __shfl_xor_sync(0xffffffffu, rs0, 2);
    rs1 += __shfl_xor_sync(0xffffffffu, rs1, 1);
    rs1 += __shfl_xor_sync(0xffffffffu, rs1, 2);
    l0 = l0 * corr0 + rs0;
    l1 = l1 * corr1 + rs1;

#pragma unroll
    for (int nt = 0; nt < 8; nt++) {
        o[nt][0] *= corr0; o[nt][1] *= corr0;
        o[nt][2] *= corr1; o[nt][3] *= corr1;
    }

#pragma unroll
    for (int kt = 0; kt < NT; kt++) {
        float p0 = s[kt][0], p1 = s[kt][1], p2 = s[kt][2], p3 = s[kt][3];
        float t0 = __shfl_sync(0xffffffffu, p0, src0);
        float t1 = __shfl_sync(0xffffffffu, p1, src0);
        float t2 = __shfl_sync(0xffffffffu, p2, src0);
        float t3 = __shfl_sync(0xffffffffu, p3, src0);
        float u0 = __shfl_sync(0xffffffffu, p0, src2);
        float u1 = __shfl_sync(0xffffffffu, p1, src2);
        float u2 = __shfl_sync(0xffffffffu, p2, src2);
        float u3 = __shfl_sync(0xffffffffu, p3, src2);
        float a0 = odd ? t1 : t0;
        float a1 = odd ? t3 : t2;
        float a2 = odd ? u1 : u0;
        float a3 = odd ? u3 : u2;
#pragma unroll
        for (int nt = 0; nt < 8; nt++) {
            float b0 = Vs[(rb + kt * 8 + qc) * VSTRW + nt * 8 + qr];
            float b1 = Vs[(rb + kt * 8 + qc + 4) * VSTRW + nt * 8 + qr];
            mma_tf32(o[nt][0], o[nt][1], o[nt][2], o[nt][3],
                     a0, a1, a2, a3, b0, b1);
        }
    }
}

__device__ __forceinline__ void calc_local(int ch, int qb, const int* __restrict__ lix,
                                           const float* __restrict__ mask_n,
                                           int tid, int (&tok)[7], float (&mv)[7])
{
    int r = tid >> 4;
#pragma unroll
    for (int i = 0; i < 7; i++) {
        int kk = ch * KC + r;
        if (kk < 288) {
            int g = qb * 96 - 96 + kk;
            if (g >= 0 && g < 3 * TT / 4) { tok[i] = lix[g]; mv[i] = mask_n[tok[i]]; }
            else { tok[i] = -1; mv[i] = NEGV; }
        } else if (kk == 288) {
            tok[i] = 0; mv[i] = 0.0f;
        } else {
            tok[i] = -1; mv[i] = NEGV;
        }
        r += 16;
    }
}

__device__ __forceinline__ void calc_global(int qb, const int* __restrict__ gix,
                                            const float* __restrict__ mask_n,
                                            int tid, int (&tok)[7], float (&mv)[7])
{
    int r = tid >> 4;
#pragma unroll
    for (int i = 0; i < 7; i++) {
        if (r < 96) {
            int half = (r >= 48) ? 1 : 0;
            int g = (2 * qb - 1 + half) * 16 + (r - half * 48);
            if (g >= 0 && g < TT / 4) { tok[i] = gix[g]; mv[i] = mask_n[tok[i]]; }
            else { tok[i] = -1; mv[i] = NEGV; }
        } else {
            tok[i] = -2;
        }
        r += 16;
    }
}

__device__ __forceinline__ void issue_K(float* __restrict__ Ks,
                                        const float* __restrict__ kb,
                                        const int (&tok)[7], int tid)
{
    int r = tid >> 4;
    int c4 = tid & 15;
#pragma unroll
    for (int i = 0; i < 7; i++) {
        float* dst = Ks + r * QSTRW + c4 * 4;
        if (tok[i] >= 0) cp16(dst, kb + (size_t)tok[i] * DD + c4 * 4);
        else if (tok[i] == -1) *(float4*)dst = make_float4(0.f, 0.f, 0.f, 0.f);
        r += 16;
    }
    cp_commit();
}

__device__ __forceinline__ void issue_V(float* __restrict__ Vs, float* __restrict__ Ms,
                                        const float* __restrict__ vb,
                                        const int (&tok)[7], const float (&mv)[7], int tid)
{
    int r = tid >> 4;
    int c4 = tid & 15;
#pragma unroll
    for (int i = 0; i < 7; i++) {
        float* dst = Vs + r * VSTRW + c4 * 4;
        if (tok[i] >= 0) cp16(dst, vb + (size_t)tok[i] * DD + c4 * 4);
        else if (tok[i] == -1) *(float4*)dst = make_float4(0.f, 0.f, 0.f, 0.f);
        if (tok[i] != -2 && c4 == 0) Ms[r] = mv[i];
        r += 16;
    }
    cp_commit();
}

__global__ __launch_bounds__(256, 2)
void attn_fused_kernel(const float* __restrict__ mask,
                       float* __restrict__ out)
{
    extern __shared__ float sm[];
    float* Qs = sm + QS_OFF;
    float* Ks = sm + KS_OFF;
    float* Vs = sm + VS_OFF;
    float* Ms = sm + MS_OFF;

    const int qb = blockIdx.x;
    const int h  = blockIdx.y;
    const int n  = blockIdx.z;
    const int tid = threadIdx.x;
    const int lane = tid & 31;
    const int warp = tid >> 5;
    const int qr = lane >> 2;
    const int qc = lane & 3;
    const int w16 = warp * 16;

    const size_t ho = (size_t)(n * NHH + h);
    const float* kb = g_ktf + ho * TT * DD;
    const float* vb = g_v + ho * TT * DD;
    const int* lix = g_lidx + ho * (3 * TT / 4);
    const int* gix = g_gidx + ho * (TT / 4);
    const float* mask_n = mask + (size_t)n * TT;

#pragma unroll
    for (int i = 0; i < 8; i++) {
        int idx = tid + i * 256;
        int r = idx >> 4, c4 = idx & 15;
        *(float4*)(Qs + r * QSTRW + c4 * 4) =
            *(const float4*)(g_q + (ho * TT + qb * 128 + r) * DD + c4 * 4);
    }

    int tok[7];
    float mv[7];
    calc_local(0, qb, lix, mask_n, tid, tok, mv);
    issue_K(Ks, kb, tok, tid);
    issue_V(Vs, Ms, vb, tok, mv, tid);

    float m0 = -1e30f, m1 = -1e30f, l0 = 0.0f, l1 = 0.0f;
    float o[8][4];
#pragma unroll
    for (int nt = 0; nt < 8; nt++)
#pragma unroll
        for (int e = 0; e < 4; e++) o[nt][e] = 0.0f;

    const int src0 = (qr << 2) + (qc >> 1);
    const int src2 = src0 + 2;
    const bool odd = (qc & 1) != 0;

    float s[14][4];

    for (int ch = 0; ch < NCH; ch++) {
        const bool glob = (ch == NCH - 1);
        cp_wait<1>();
        __syncthreads();

        int rb = 0;
        if (!glob) {
            compute_S<14>(Qs, Ks, s, 0, w16, qr, qc);
        } else {
            rb = (warp >= 4) ? 48 : 0;
            compute_S<6>(Qs, Ks, s, rb, w16, qr, qc);
        }
        __syncthreads();

        if (ch + 1 < NCH) {
            if (ch + 1 == NCH - 1) calc_global(qb, gix, mask_n, tid, tok, mv);
            else                   calc_local(ch + 1, qb, lix, mask_n, tid, tok, mv);
            issue_K(Ks, kb, tok, tid);
            cp_wait<1>();
        } else {
            cp_wait<0>();
        }
        __syncthreads();

        if (!glob)
            softmax_pv<14>(Vs, Ms, s, 0, w16, qr, qc, src0, src2, odd,
                           m0, m1, l0, l1, o);
        else
            softmax_pv<6>(Vs, Ms, s, rb, w16, qr, qc, src0, src2, odd,
                          m0, m1, l0, l1, o);
        __syncthreads();

        if (ch + 1 < NCH)
            issue_V(Vs, Ms, vb, tok, mv, tid);
    }

    float inv0 = 1.0f / l0;
    float inv1 = 1.0f / l1;
    int row0 = qb * 128 + w16 + qr;
    int row1 = row0 + 8;
    float* op0 = out + ((size_t)n * TT + row0) * HIDD + h * DD;
    float* op1 = out + ((size_t)n * TT + row1) * HIDD + h * DD;
#pragma unroll
    for (int nt = 0; nt < 8; nt++) {
        int c0 = nt * 8 + 2 * qc;
#pragma unroll
        for (int e = 0; e < 2; e++) {
            op0[c0 + e] = o[nt][e] * inv0;
            op1[c0 + e] = o[nt][2 + e] * inv1;
        }
    }
}

// ---------------- BOS row ----------------------------------------------------------
__global__ void bos_kernel(const float* __restrict__ mask,
                           float* __restrict__ out)
{
    const int h = blockIdx.x;
    const int n = blockIdx.y;
    const int tid = threadIdx.x;
    __shared__ float sc[TT];
    __shared__ float qs[64];
    __shared__ float red[128];

    const size_t ho = (size_t)(n * NHH + h);
    const float* kb = g_k + ho * TT * DD;
    const float* vb = g_v + ho * TT * DD;
    if (tid < 64) qs[tid] = g_q0[(size_t)n * HIDD + h * DD + tid];
    __syncthreads();

    float lmax = -1e30f;
    for (int t = tid; t < TT; t += 128) {
        const float* kr = kb + (size_t)t * DD;
        float dot = 0.0f;
#pragma unroll
        for (int d = 0; d < 64; d++) dot = fmaf(qs[d], kr[d], dot);
        float s = dot + mask[n * TT + t];
        sc[t] = s;
        lmax = fmaxf(lmax, s);
    }
    red[tid] = lmax;
    __syncthreads();
    for (int off = 64; off > 0; off >>= 1) {
        if (tid < off) red[tid] = fmaxf(red[tid], red[tid + off]);
        __syncthreads();
    }
    float mmax = red[0];
    float lsum = 0.0f;
    for (int t = tid; t < TT; t += 128) {
        float p = __expf(sc[t] - mmax);
        sc[t] = p;
        lsum += p;
    }
    __syncthreads();
    red[tid] = lsum;
    __syncthreads();
    for (int off = 64; off > 0; off >>= 1) {
        if (tid < off) red[tid] += red[tid + off];
        __syncthreads();
    }
    float inv = 1.0f / red[0];
    __syncthreads();
    {
        int half = tid >> 6;
        int d = tid & 63;
        float acc = 0.0f;
        int t0 = half * (TT / 2);
        for (int t = t0; t < t0 + TT / 2; t++)
            acc = fmaf(sc[t], vb[(size_t)t * DD + d], acc);
        red[tid] = acc;
    }
    __syncthreads();
    if (tid < 64)
        out[((size_t)n * TT) * HIDD + h * DD + tid] =
            (red[tid] + red[tid + 64]) * inv;
}

// ---------------- launch ----------------------------------------------------------
extern "C" void kernel_launch(void* const* d_in, const int* in_sizes, int n_in,
                              void* d_out, int out_size)
{
    (void)in_sizes; (void)n_in; (void)out_size;
    const float* hs   = (const float*)d_in[0];
    const float* mask = (const float*)d_in[1];
    const float* Wq   = (const float*)d_in[2];
    const float* bq   = (const float*)d_in[3];
    const float* Wk   = (const float*)d_in[4];
    const float* bk   = (const float*)d_in[5];
    const float* Wv   = (const float*)d_in[6];
    const float* bv   = (const float*)d_in[7];
    float* out = (float*)d_out;

    float *qp, *kp, *ktfp, *vp;
    cudaGetSymbolAddress((void**)&qp, g_q);
    cudaGetSymbolAddress((void**)&kp, g_k);
    cudaGetSymbolAddress((void**)&ktfp, g_ktf);
    cudaGetSymbolAddress((void**)&vp, g_v);
    uint2 *afh, *afl, *wfh, *wfl;
    cudaGetSymbolAddress((void**)&afh, g_Afh4);
    cudaGetSymbolAddress((void**)&afl, g_Afl4);
    cudaGetSymbolAddress((void**)&wfh, g_Wfh4);
    cudaGetSymbolAddress((void**)&wfl, g_Wfl4);

    {
        int n4a = NB * TT * HIDD / 4;
        cvt_a_kernel<<<(n4a + 255) / 256, 256>>>(hs, afh, afl, n4a);
        int n4w = HIDD * HIDD / 4;
        cvt_w_kernel<<<dim3((n4w + 255) / 256, 3), 256>>>(Wq, Wk, Wv, wfh, wfl, n4w);
        q0_kernel<<<dim3(HIDD, NB), 128>>>(hs, Wq, bq);
    }

    {
        cudaFuncSetAttribute(gemm_all_kernel,
                             cudaFuncAttributeMaxDynamicSharedMemorySize, GSMEMB);
        gemm_all_kernel<<<dim3(HIDD / 128, (NB * TT) / 128, 3), 256, GSMEMB>>>(
            bq, bk, bv, qp, kp, ktfp, vp);
    }

    select_kernel<<<dim3(TT / 256, NHH, NB), 256>>>(mask, bq);

    size_t lsmem = (size_t)LSMEM_WORDS * sizeof(float);
    cudaFuncSetAttribute(attn_fused_kernel,
                         cudaFuncAttributeMaxDynamicSharedMemorySize, (int)lsmem);
    attn_fused_kernel<<<dim3(TT / 128, NHH, NB), 256, lsmem>>>(mask, out);

    bos_kernel<<<dim3(NHH, NB), 128>>>(mask, out);
}

// round 15
// speedup vs baseline: 1.0477x; 1.0477x over previous
#include <cuda_runtime.h>
#include <cuda_bf16.h>
#include <cuda_fp16.h>
#include <math.h>

#define NB   2
#define TT   4096
#define HIDD 1024
#define NHH  16
#define DD   64
#define TOPKK 16
#define NEGV (-10000.0f)

// ---------------- device scratch ----------------
__device__ float g_q[(size_t)NB*NHH*TT*DD];     // tf32-rounded (attn only)
__device__ float g_k[(size_t)NB*NHH*TT*DD];     // exact (selection, bos)
__device__ float g_ktf[(size_t)NB*NHH*TT*DD];   // tf32-rounded (attn)
__device__ float g_v[(size_t)NB*NHH*TT*DD];     // tf32-rounded (attn, bos)
__device__ float g_q0[(size_t)NB*HIDD];
__device__ int   g_gidx[(size_t)NB*NHH*(TT/4)];
__device__ int   g_lidx[(size_t)NB*NHH*(3*TT/4)];
__device__ uint4 g_Afh4[(size_t)NB*TT*HIDD/8];
__device__ uint4 g_Afl4[(size_t)NB*TT*HIDD/8];
__device__ uint4 g_Wfh4[(size_t)3*HIDD*HIDD/8];  // 0=Wq, 1=Wv, 2=Wk
__device__ uint4 g_Wfl4[(size_t)HIDD*HIDD/8];    // Wk lo

// ---------------- helpers ----------------
__device__ __forceinline__ void mma_f16(float& d0, float& d1, float& d2, float& d3,
                                        unsigned a0, unsigned a1, unsigned a2, unsigned a3,
                                        unsigned b0, unsigned b1)
{
    asm("mma.sync.aligned.m16n8k16.row.col.f32.f16.f16.f32 "
        "{%0,%1,%2,%3}, {%4,%5,%6,%7}, {%8,%9}, {%0,%1,%2,%3};\n"
        : "+f"(d0), "+f"(d1), "+f"(d2), "+f"(d3)
        : "r"(a0), "r"(a1), "r"(a2), "r"(a3), "r"(b0), "r"(b1));
}

__device__ __forceinline__ void ldsm4(unsigned& r0, unsigned& r1,
                                      unsigned& r2, unsigned& r3, unsigned saddr)
{
    asm volatile("ldmatrix.sync.aligned.m8n8.x4.shared.b16 {%0,%1,%2,%3}, [%4];"
                 : "=r"(r0), "=r"(r1), "=r"(r2), "=r"(r3) : "r"(saddr));
}

__device__ __forceinline__ void cp16(void* smem_dst, const void* gsrc)
{
    unsigned saddr = (unsigned)__cvta_generic_to_shared(smem_dst);
    asm volatile("cp.async.ca.shared.global [%0], [%1], 16;\n"
                 :: "r"(saddr), "l"(gsrc));
}
__device__ __forceinline__ void cp_commit()
{
    asm volatile("cp.async.commit_group;\n" ::: "memory");
}
template <int N> __device__ __forceinline__ void cp_wait()
{
    asm volatile("cp.async.wait_group %0;\n" :: "n"(N) : "memory");
}

__device__ __forceinline__ float to_tf32(float x)
{
    float r;
    asm("cvt.rna.tf32.f32 %0, %1;" : "=f"(r) : "f"(x));
    return r;
}

__device__ __forceinline__ void mma_tf32(float& d0, float& d1, float& d2, float& d3,
                                         float a0, float a1, float a2, float a3,
                                         float b0, float b1)
{
    asm("mma.sync.aligned.m16n8k8.row.col.f32.tf32.tf32.f32 "
        "{%0,%1,%2,%3}, {%4,%5,%6,%7}, {%8,%9}, {%0,%1,%2,%3};\n"
        : "+f"(d0), "+f"(d1), "+f"(d2), "+f"(d3)
        : "r"(__float_as_uint(a0)), "r"(__float_as_uint(a1)),
          "r"(__float_as_uint(a2)), "r"(__float_as_uint(a3)),
          "r"(__float_as_uint(b0)), "r"(__float_as_uint(b1)));
}

// ---------------- conversions ------------------------------------------------------
__device__ __forceinline__ uint2 pack_hi4(float4 v)
{
    __half h0 = __float2half_rn(v.x), h1 = __float2half_rn(v.y);
    __half h2 = __float2half_rn(v.z), h3 = __float2half_rn(v.w);
    return make_uint2((unsigned)__half_as_ushort(h0) | ((unsigned)__half_as_ushort(h1) << 16),
                      (unsigned)__half_as_ushort(h2) | ((unsigned)__half_as_ushort(h3) << 16));
}
__device__ __forceinline__ uint2 pack_lo4(float4 v)
{
    __half h0 = __float2half_rn(v.x), h1 = __float2half_rn(v.y);
    __half h2 = __float2half_rn(v.z), h3 = __float2half_rn(v.w);
    __half l0 = __float2half_rn(v.x - __half2float(h0));
    __half l1 = __float2half_rn(v.y - __half2float(h1));
    __half l2 = __float2half_rn(v.z - __half2float(h2));
    __half l3 = __float2half_rn(v.w - __half2float(h3));
    return make_uint2((unsigned)__half_as_ushort(l0) | ((unsigned)__half_as_ushort(l1) << 16),
                      (unsigned)__half_as_ushort(l2) | ((unsigned)__half_as_ushort(l3) << 16));
}

__global__ void cvt_a_kernel(const float* __restrict__ in,
                             uint2* __restrict__ fh, uint2* __restrict__ fl, int n4)
{
    int i = blockIdx.x * blockDim.x + threadIdx.x;
    if (i >= n4) return;
    float4 v = ((const float4*)in)[i];
    fh[i] = pack_hi4(v);
    fl[i] = pack_lo4(v);
}

__global__ void cvt_w_kernel(const float* __restrict__ Wq,
                             const float* __restrict__ Wk,
                             const float* __restrict__ Wv,
                             uint2* __restrict__ fh, uint2* __restrict__ fl, int n4)
{
    int i = blockIdx.x * blockDim.x + threadIdx.x;
    if (i >= n4) return;
    int w = blockIdx.y;
    const float* in = (w == 0) ? Wq : (w == 1) ? Wk : Wv;
    int slot = (w == 0) ? 0 : (w == 1) ? 2 : 1;
    float4 v = ((const float4*)in)[i];
    fh[(size_t)slot * n4 + i] = pack_hi4(v);
    if (w == 1) fl[i] = pack_lo4(v);
}

__global__ void q0_kernel(const float* __restrict__ hs,
                          const float* __restrict__ Wq,
                          const float* __restrict__ bq)
{
    const int c = blockIdx.x;
    const int n = blockIdx.y;
    const int tid = threadIdx.x;
    __shared__ float red[128];
    const float* xr = hs + (size_t)n * TT * HIDD;
    const float* wr = Wq + (size_t)c * HIDD;
    float pa = 0.0f;
    for (int k = tid; k < HIDD; k += 128) pa = fmaf(xr[k], wr[k], pa);
    red[tid] = pa;
    __syncthreads();
    for (int off = 64; off > 0; off >>= 1) {
        if (tid < off) red[tid] += red[tid + off];
        __syncthreads();
    }
    if (tid == 0) g_q0[(size_t)n * HIDD + c] = red[0] + bq[c];
}

// ============= fused QKV GEMM: per-output term counts =============================
// z=0 Q: 1 term (hi*hi). z=1 V: 2 terms (+lo_a*hi_b). z=2 K: 3 terms (+hi_a*lo_b).
#define KSTR 16
#define PLW  (128 * KSTR)
#define PA_HI 0
#define PA_LO (1 * PLW)
#define PB_HI (2 * PLW)
#define PB_LO (3 * PLW)
#define STGW  (4 * PLW)
#define GSMEMB (3 * STGW * 4)          /* 96KB */

__global__ __launch_bounds__(256, 2)
void gemm_all_kernel(const float* __restrict__ bq,
                     const float* __restrict__ bk,
                     const float* __restrict__ bv,
                     float* __restrict__ oq,
                     float* __restrict__ ok,
                     float* __restrict__ oktf,
                     float* __restrict__ ov)
{
    extern __shared__ unsigned gsm[];
    const int tid = threadIdx.x;
    const int m0 = blockIdx.y * 128;
    const int n0 = blockIdx.x * 128;
    const int z  = blockIdx.z;
    const bool isK = (z == 2);
    const bool useALo = (z != 0);      // V and K need the A-lo term

    const char* Ah = (const char*)((const __half*)g_Afh4 + (size_t)m0 * HIDD);
    const char* Al = (const char*)((const __half*)g_Afl4 + (size_t)m0 * HIDD);
    const char* Bh = (const char*)((const __half*)g_Wfh4 + ((size_t)z * HIDD + n0) * HIDD);
    const char* Bl = (const char*)((const __half*)g_Wfl4 + (size_t)n0 * HIDD);
    const float* bias = (z == 0) ? bq : (z == 1) ? bv : bk;

    const int lane = tid & 31;
    const int warp = tid >> 5;
    const int wm = warp >> 1;
    const int wn = warp & 1;
    const int qr = lane >> 2;
    const int qc = lane & 3;
    const int rA = wm * 32;
    const int cB = wn * 64;

    const unsigned smem_base = (unsigned)__cvta_generic_to_shared(gsm);
    const int a_r0 = rA + (lane & 7) + ((lane >> 3) & 1) * 8;
    const unsigned a_kbit = (lane >> 4) & 1;
    const int b_r0 = cB + (lane & 7) + ((lane >> 4) & 1) * 8;
    const unsigned b_kbit = (lane >> 3) & 1;

    float acc[2][8][4];
#pragma unroll
    for (int mt = 0; mt < 2; mt++)
#pragma unroll
        for (int nt = 0; nt < 8; nt++)
#pragma unroll
            for (int e = 0; e < 4; e++) acc[mt][nt][e] = 0.0f;

    auto load_stage = [&](int buf, int kofs) {
        unsigned* st = gsm + buf * STGW;
#pragma unroll
        for (int i = 0; i < 2; i++) {
            int c = tid + i * 256;
            int row = c >> 2;
            int cw = c & 3;
            size_t go = ((size_t)row * HIDD + kofs + cw * 8) * 2;
            int pw = (cw ^ ((row >> 1) & 3)) * 4;
            unsigned* sp = st + row * KSTR + pw;
            cp16(sp + PA_HI, Ah + go);
            if (useALo) cp16(sp + PA_LO, Al + go);
            cp16(sp + PB_HI, Bh + go);
            if (isK) cp16(sp + PB_LO, Bl + go);
        }
        cp_commit();
    };

    load_stage(0, 0);
    load_stage(1, 32);

    const int NIT = HIDD / 32;
    int cur = 0;
    for (int it = 0; it < NIT; it++) {
        if (it + 1 < NIT) cp_wait<1>(); else cp_wait<0>();
        __syncthreads();
        if (it + 2 < NIT) {
            int s2 = cur + 2; if (s2 >= 3) s2 -= 3;
            load_stage(s2, (it + 2) * 32);
        }

        const unsigned sb = smem_base + cur * (STGW * 4);
#pragma unroll
        for (int s = 0; s < 2; s++) {
            unsigned a_hi[2][4], a_lo[2][4];
#pragma unroll
            for (int mt = 0; mt < 2; mt++) {
                int row = a_r0 + mt * 16;
                unsigned kc = (unsigned)s * 2 + a_kbit;
                unsigned ao = (unsigned)row * 64 + ((kc ^ ((unsigned)(row >> 1) & 3u)) << 4);
                ldsm4(a_hi[mt][0], a_hi[mt][1], a_hi[mt][2], a_hi[mt][3],
                      sb + PA_HI * 4 + ao);
                if (useALo)
                    ldsm4(a_lo[mt][0], a_lo[mt][1], a_lo[mt][2], a_lo[mt][3],
                          sb + PA_LO * 4 + ao);
            }
#pragma unroll
            for (int ph = 0; ph < 2; ph++) {
                unsigned bh[2][4], bl[2][4];
#pragma unroll
                for (int pp = 0; pp < 2; pp++) {
                    int p = ph * 2 + pp;
                    int row = b_r0 + p * 16;
                    unsigned kc = (unsigned)s * 2 + b_kbit;
                    unsigned bo = (unsigned)row * 64 + ((kc ^ ((unsigned)(row >> 1) & 3u)) << 4);
                    ldsm4(bh[pp][0], bh[pp][1], bh[pp][2], bh[pp][3],
                          sb + PB_HI * 4 + bo);
                    if (isK)
                        ldsm4(bl[pp][0], bl[pp][1], bl[pp][2], bl[pp][3],
                              sb + PB_LO * 4 + bo);
                }
                // term 1: hi*hi (always)
#pragma unroll
                for (int pp = 0; pp < 2; pp++) {
                    int p = ph * 2 + pp;
#pragma unroll
                    for (int mt = 0; mt < 2; mt++) {
                        float* c0 = acc[mt][2 * p];
                        float* c1 = acc[mt][2 * p + 1];
                        mma_f16(c0[0], c0[1], c0[2], c0[3],
                                a_hi[mt][0], a_hi[mt][1], a_hi[mt][2], a_hi[mt][3],
                                bh[pp][0], bh[pp][1]);
                        mma_f16(c1[0], c1[1], c1[2], c1[3],
                                a_hi[mt][0], a_hi[mt][1], a_hi[mt][2], a_hi[mt][3],
                                bh[pp][2], bh[pp][3]);
                    }
                }
                // term 2: lo_a*hi_b (V and K)
                if (useALo) {
#pragma unroll
                    for (int pp = 0; pp < 2; pp++) {
                        int p = ph * 2 + pp;
#pragma unroll
                        for (int mt = 0; mt < 2; mt++) {
                            float* c0 = acc[mt][2 * p];
                            float* c1 = acc[mt][2 * p + 1];
                            mma_f16(c0[0], c0[1], c0[2], c0[3],
                                    a_lo[mt][0], a_lo[mt][1], a_lo[mt][2], a_lo[mt][3],
                                    bh[pp][0], bh[pp][1]);
                            mma_f16(c1[0], c1[1], c1[2], c1[3],
                                    a_lo[mt][0], a_lo[mt][1], a_lo[mt][2], a_lo[mt][3],
                                    bh[pp][2], bh[pp][3]);
                        }
                    }
                }
                // term 3: hi_a*lo_b (K only)
                if (isK) {
#pragma unroll
                    for (int pp = 0; pp < 2; pp++) {
                        int p = ph * 2 + pp;
#pragma unroll
                        for (int mt = 0; mt < 2; mt++) {
                            float* c0 = acc[mt][2 * p];
                            float* c1 = acc[mt][2 * p + 1];
                            mma_f16(c0[0], c0[1], c0[2], c0[3],
                                    a_hi[mt][0], a_hi[mt][1], a_hi[mt][2], a_hi[mt][3],
                                    bl[pp][0], bl[pp][1]);
                            mma_f16(c1[0], c1[1], c1[2], c1[3],
                                    a_hi[mt][0], a_hi[mt][1], a_hi[mt][2], a_hi[mt][3],
                                    bl[pp][2], bl[pp][3]);
                        }
                    }
                }
            }
        }
        cur = (cur + 1 == 3) ? 0 : cur + 1;
    }

#pragma unroll
    for (int mt = 0; mt < 2; mt++) {
#pragma unroll
        for (int nt = 0; nt < 8; nt++) {
#pragma unroll
            for (int half = 0; half < 2; half++) {
                int row = m0 + rA + mt * 16 + qr + half * 8;
                int nb  = row >> 12;
                int t   = row & (TT - 1);
                int col = n0 + cB + nt * 8 + qc * 2;
                int h = col >> 6;
                int d = col & 63;
                size_t off = (((size_t)(nb * NHH + h)) * TT + t) * DD + d;
                float v0 = acc[mt][nt][half * 2 + 0] + bias[col];
                float v1 = acc[mt][nt][half * 2 + 1] + bias[col + 1];
                if (isK) {
                    ok[off] = v0; ok[off + 1] = v1;
                    oktf[off] = to_tf32(v0); oktf[off + 1] = to_tf32(v1);
                } else {
                    float* op = (z == 0) ? oq : ov;
                    op[off] = to_tf32(v0); op[off + 1] = to_tf32(v1);
                }
            }
        }
    }
}

// ---------------- top-k selection (exact g_k) -------------------------------------
__global__ void select_kernel(const float* __restrict__ mask,
                              const float* __restrict__ bq)
{
    const int sub = threadIdx.x >> 6;
    const int i   = threadIdx.x & 63;
    const int blk = blockIdx.x * 4 + sub;
    const int h   = blockIdx.y;
    const int n   = blockIdx.z;
    __shared__ float norms[4][64];
    __shared__ int flags[4][64];

    const int token = blk * 64 + i;
    const float* kr = g_k + (((size_t)(n * NHH + h)) * TT + token) * DD;
    const float* bqr = bq + h * DD;
    float s = 0.0f;
#pragma unroll
    for (int d = 0; d < DD; d++) { float vv = kr[d] + bqr[d]; s += vv * vv; }
    if (mask[n * TT + token] != 0.0f) s = 0.0f;
    norms[sub][i] = s;
    __syncthreads();

    float mine = norms[sub][i];
    int rank = 0;
    for (int j = 0; j < 64; j++) {
        float nj = norms[sub][j];
        rank += (nj < mine) || (nj == mine && j < i);
    }
    int top = (rank >= 64 - TOPKK) ? 1 : 0;
    flags[sub][i] = top;
    __syncthreads();

    int pos = 0;
    for (int j = 0; j < i; j++) pos += flags[sub][j];
    if (top)
        g_gidx[((size_t)(n * NHH + h)) * (TT / 4) + blk * TOPKK + pos] = token;
    else
        g_lidx[((size_t)(n * NHH + h)) * (3 * TT / 4) + blk * 48 + (i - pos)] = token;
}

// ======== fused local+global flash, cp.async-pipelined gathers ====================
#define KC     112
#define NCH    4
#define QSTRW  68
#define VSTRW  72
#define QS_OFF 0
#define KS_OFF (QS_OFF + 128*QSTRW)
#define VS_OFF (KS_OFF + KC*QSTRW)
#define MS_OFF (VS_OFF + KC*VSTRW)
#define LSMEM_WORDS (MS_OFF + KC)

template <int NT>
__device__ __forceinline__ void compute_S(
    const float* __restrict__ Qs, const float* __restrict__ Ks,
    float (&s)[14][4], int rb, int w16, int qr, int qc)
{
#pragma unroll
    for (int nt = 0; nt < NT; nt++) {
        s[nt][0] = 0.f; s[nt][1] = 0.f; s[nt][2] = 0.f; s[nt][3] = 0.f;
    }
#pragma unroll
    for (int k8 = 0; k8 < 8; k8++) {
        const int kc0 = k8 * 8 + qc;
        float a0 = Qs[(w16 + qr) * QSTRW + kc0];
        float a1 = Qs[(w16 + qr + 8) * QSTRW + kc0];
        float a2 = Qs[(w16 + qr) * QSTRW + kc0 + 4];
        float a3 = Qs[(w16 + qr + 8) * QSTRW + kc0 + 4];
#pragma unroll
        for (int nt = 0; nt < NT; nt++) {
            float b0 = Ks[(rb + nt * 8 + qr) * QSTRW + kc0];
            float b1 = Ks[(rb + nt * 8 + qr) * QSTRW + kc0 + 4];
            mma_tf32(s[nt][0], s[nt][1], s[nt][2], s[nt][3],
                     a0, a1, a2, a3, b0, b1);
        }
    }
}

template <int NT>
__device__ __forceinline__ void softmax_pv(
    const float* __restrict__ Vs, const float* __restrict__ Ms,
    float (&s)[14][4], int rb, int w16, int qr, int qc,
    int src0, int src2, bool odd,
    float& m0, float& m1, float& l0, float& l1, float (&o)[8][4])
{
    float cmax0 = -1e30f, cmax1 = -1e30f;
#pragma unroll
    for (int nt = 0; nt < NT; nt++) {
        float mc0 = Ms[rb + nt * 8 + 2 * qc];
        float mc1 = Ms[rb + nt * 8 + 2 * qc + 1];
        s[nt][0] = s[nt][0] * 0.125f + mc0;
        s[nt][1] = s[nt][1] * 0.125f + mc1;
        s[nt][2] = s[nt][2] * 0.125f + mc0;
        s[nt][3] = s[nt][3] * 0.125f + mc1;
        cmax0 = fmaxf(cmax0, fmaxf(s[nt][0], s[nt][1]));
        cmax1 = fmaxf(cmax1, fmaxf(s[nt][2], s[nt][3]));
    }
    cmax0 = fmaxf(cmax0, __shfl_xor_sync(0xffffffffu, cmax0, 1));
    cmax0 = fmaxf(cmax0, __shfl_xor_sync(0xffffffffu, cmax0, 2));
    cmax1 = fmaxf(cmax1, __shfl_xor_sync(0xffffffffu, cmax1, 1));
    cmax1 = fmaxf(cmax1, __shfl_xor_sync(0xffffffffu, cmax1, 2));

    float mn0 = fmaxf(m0, cmax0);
    float mn1 = fmaxf(m1, cmax1);
    float corr0 = __expf(m0 - mn0);
    float corr1 = __expf(m1 - mn1);
    m0 = mn0; m1 = mn1;

    float rs0 = 0.0f, rs1 = 0.0f;
#pragma unroll
    for (int nt = 0; nt < NT; nt++) {
        float p0 = __expf(s[nt][0] - mn0);
        float p1 = __expf(s[nt][1] - mn0);
        float p2 = __expf(s[nt][2] - mn1);
        float p3 = __expf(s[nt][3] - mn1);
        rs0 += p0 + p1; rs1 += p2 + p3;
        s[nt][0] = to_tf32(p0); s[nt][1] = to_tf32(p1);
        s[nt][2] = to_tf32(p2); s[nt][3] = to_tf32(p3);
    }
    rs0 += __shfl_xor_sync(0xffffffffu, rs0, 1);
    rs0 += __shfl_xor_sync(0xffffffffu, rs0, 2);
    rs1 += __shfl_xor_sync(0xffffffffu, rs1, 1);
    rs1 += __shfl_xor_sync(0xffffffffu, rs1, 2);
    l0 = l0 * corr0 + rs0;
    l1 = l1 * corr1 + rs1;

#pragma unroll
    for (int nt = 0; nt < 8; nt++) {
        o[nt][0] *= corr0; o[nt][1] *= corr0;
        o[nt][2] *= corr1; o[nt][3] *= corr1;
    }

#pragma unroll
    for (int kt = 0; kt < NT; kt++) {
        float p0 = s[kt][0], p1 = s[kt][1], p2 = s[kt][2], p3 = s[kt][3];
        float t0 = __shfl_sync(0xffffffffu, p0, src0);
        float t1 = __shfl_sync(0xffffffffu, p1, src0);
        float t2 = __shfl_sync(0xffffffffu, p2, src0);
        float t3 = __shfl_sync(0xffffffffu, p3, src0);
        float u0 = __shfl_sync(0xffffffffu, p0, src2);
        float u1 = __shfl_sync(0xffffffffu, p1, src2);
        float u2 = __shfl_sync(0xffffffffu, p2, src2);
        float u3 = __shfl_sync(0xffffffffu, p3, src2);
        float a0 = odd ? t1 : t0;
        float a1 = odd ? t3 : t2;
        float a2 = odd ? u1 : u0;
        float a3 = odd ? u3 : u2;
#pragma unroll
        for (int nt = 0; nt < 8; nt++) {
            float b0 = Vs[(rb + kt * 8 + qc) * VSTRW + nt * 8 + qr];
            float b1 = Vs[(rb + kt * 8 + qc + 4) * VSTRW + nt * 8 + qr];
            mma_tf32(o[nt][0], o[nt][1], o[nt][2], o[nt][3],
                     a0, a1, a2, a3, b0, b1);
        }
    }
}

__device__ __forceinline__ void calc_local(int ch, int qb, const int* __restrict__ lix,
                                           const float* __restrict__ mask_n,
                                           int tid, int (&tok)[7], float (&mv)[7])
{
    int r = tid >> 4;
#pragma unroll
    for (int i = 0; i < 7; i++) {
        int kk = ch * KC + r;
        if (kk < 288) {
            int g = qb * 96 - 96 + kk;
            if (g >= 0 && g < 3 * TT / 4) { tok[i] = lix[g]; mv[i] = mask_n[tok[i]]; }
            else { tok[i] = -1; mv[i] = NEGV; }
        } else if (kk == 288) {
            tok[i] = 0; mv[i] = 0.0f;
        } else {
            tok[i] = -1; mv[i] = NEGV;
        }
        r += 16;
    }
}

__device__ __forceinline__ void calc_global(int qb, const int* __restrict__ gix,
                                            const float* __restrict__ mask_n,
                                            int tid, int (&tok)[7], float (&mv)[7])
{
    int r = tid >> 4;
#pragma unroll
    for (int i = 0; i < 7; i++) {
        if (r < 96) {
            int half = (r >= 48) ? 1 : 0;
            int g = (2 * qb - 1 + half) * 16 + (r - half * 48);
            if (g >= 0 && g < TT / 4) { tok[i] = gix[g]; mv[i] = mask_n[tok[i]]; }
            else { tok[i] = -1; mv[i] = NEGV; }
        } else {
            tok[i] = -2;
        }
        r += 16;
    }
}

__device__ __forceinline__ void issue_K(float* __restrict__ Ks,
                                        const float* __restrict__ kb,
                                        const int (&tok)[7], int tid)
{
    int r = tid >> 4;
    int c4 = tid & 15;
#pragma unroll
    for (int i = 0; i < 7; i++) {
        float* dst = Ks + r * QSTRW + c4 * 4;
        if (tok[i] >= 0) cp16(dst, kb + (size_t)tok[i] * DD + c4 * 4);
        else if (tok[i] == -1) *(float4*)dst = make_float4(0.f, 0.f, 0.f, 0.f);
        r += 16;
    }
    cp_commit();
}

__device__ __forceinline__ void issue_V(float* __restrict__ Vs, float* __restrict__ Ms,
                                        const float* __restrict__ vb,
                                        const int (&tok)[7], const float (&mv)[7], int tid)
{
    int r = tid >> 4;
    int c4 = tid & 15;
#pragma unroll
    for (int i = 0; i < 7; i++) {
        float* dst = Vs + r * VSTRW + c4 * 4;
        if (tok[i] >= 0) cp16(dst, vb + (size_t)tok[i] * DD + c4 * 4);
        else if (tok[i] == -1) *(float4*)dst = make_float4(0.f, 0.f, 0.f, 0.f);
        if (tok[i] != -2 && c4 == 0) Ms[r] = mv[i];
        r += 16;
    }
    cp_commit();
}

__global__ __launch_bounds__(256, 2)
void attn_fused_kernel(const float* __restrict__ mask,
                       float* __restrict__ out)
{
    extern __shared__ float sm[];
    float* Qs = sm + QS_OFF;
    float* Ks = sm + KS_OFF;
    float* Vs = sm + VS_OFF;
    float* Ms = sm + MS_OFF;

    const int qb = blockIdx.x;
    const int h  = blockIdx.y;
    const int n  = blockIdx.z;
    const int tid = threadIdx.x;
    const int lane = tid & 31;
    const int warp = tid >> 5;
    const int qr = lane >> 2;
    const int qc = lane & 3;
    const int w16 = warp * 16;

    const size_t ho = (size_t)(n * NHH + h);
    const float* kb = g_ktf + ho * TT * DD;
    const float* vb = g_v + ho * TT * DD;
    const int* lix = g_lidx + ho * (3 * TT / 4);
    const int* gix = g_gidx + ho * (TT / 4);
    const float* mask_n = mask + (size_t)n * TT;

#pragma unroll
    for (int i = 0; i < 8; i++) {
        int idx = tid + i * 256;
        int r = idx >> 4, c4 = idx & 15;
        *(float4*)(Qs + r * QSTRW + c4 * 4) =
            *(const float4*)(g_q + (ho * TT + qb * 128 + r) * DD + c4 * 4);
    }

    int tok[7];
    float mv[7];
    calc_local(0, qb, lix, mask_n, tid, tok, mv);
    issue_K(Ks, kb, tok, tid);
    issue_V(Vs, Ms, vb, tok, mv, tid);

    float m0 = -1e30f, m1 = -1e30f, l0 = 0.0f, l1 = 0.0f;
    float o[8][4];
#pragma unroll
    for (int nt = 0; nt < 8; nt++)
#pragma unroll
        for (int e = 0; e < 4; e++) o[nt][e] = 0.0f;

    const int src0 = (qr << 2) + (qc >> 1);
    const int src2 = src0 + 2;
    const bool odd = (qc & 1) != 0;

    float s[14][4];

    for (int ch = 0; ch < NCH; ch++) {
        const bool glob = (ch == NCH - 1);
        cp_wait<1>();
        __syncthreads();

        int rb = 0;
        if (!glob) {
            compute_S<14>(Qs, Ks, s, 0, w16, qr, qc);
        } else {
            rb = (warp >= 4) ? 48 : 0;
            compute_S<6>(Qs, Ks, s, rb, w16, qr, qc);
        }
        __syncthreads();

        if (ch + 1 < NCH) {
            if (ch + 1 == NCH - 1) calc_global(qb, gix, mask_n, tid, tok, mv);
            else                   calc_local(ch + 1, qb, lix, mask_n, tid, tok, mv);
            issue_K(Ks, kb, tok, tid);
            cp_wait<1>();
        } else {
            cp_wait<0>();
        }
        __syncthreads();

        if (!glob)
            softmax_pv<14>(Vs, Ms, s, 0, w16, qr, qc, src0, src2, odd,
                           m0, m1, l0, l1, o);
        else
            softmax_pv<6>(Vs, Ms, s, rb, w16, qr, qc, src0, src2, odd,
                          m0, m1, l0, l1, o);
        __syncthreads();

        if (ch + 1 < NCH)
            issue_V(Vs, Ms, vb, tok, mv, tid);
    }

    float inv0 = 1.0f / l0;
    float inv1 = 1.0f / l1;
    int row0 = qb * 128 + w16 + qr;
    int row1 = row0 + 8;
    float* op0 = out + ((size_t)n * TT + row0) * HIDD + h * DD;
    float* op1 = out + ((size_t)n * TT + row1) * HIDD + h * DD;
#pragma unroll
    for (int nt = 0; nt < 8; nt++) {
        int c0 = nt * 8 + 2 * qc;
#pragma unroll
        for (int e = 0; e < 2; e++) {
            op0[c0 + e] = o[nt][e] * inv0;
            op1[c0 + e] = o[nt][2 + e] * inv1;
        }
    }
}

// ---------------- BOS row ----------------------------------------------------------
__global__ void bos_kernel(const float* __restrict__ mask,
                           float* __restrict__ out)
{
    const int h = blockIdx.x;
    const int n = blockIdx.y;
    const int tid = threadIdx.x;
    __shared__ float sc[TT];
    __shared__ float qs[64];
    __shared__ float red[128];

    const size_t ho = (size_t)(n * NHH + h);
    const float* kb = g_k + ho * TT * DD;
    const float* vb = g_v + ho * TT * DD;
    if (tid < 64) qs[tid] = g_q0[(size_t)n * HIDD + h * DD + tid];
    __syncthreads();

    float lmax = -1e30f;
    for (int t = tid; t < TT; t += 128) {
        const float* kr = kb + (size_t)t * DD;
        float dot = 0.0f;
#pragma unroll
        for (int d = 0; d < 64; d++) dot = fmaf(qs[d], kr[d], dot);
        float s = dot + mask[n * TT + t];
        sc[t] = s;
        lmax = fmaxf(lmax, s);
    }
    red[tid] = lmax;
    __syncthreads();
    for (int off = 64; off > 0; off >>= 1) {
        if (tid < off) red[tid] = fmaxf(red[tid], red[tid + off]);
        __syncthreads();
    }
    float mmax = red[0];
    float lsum = 0.0f;
    for (int t = tid; t < TT; t += 128) {
        float p = __expf(sc[t] - mmax);
        sc[t] = p;
        lsum += p;
    }
    __syncthreads();
    red[tid] = lsum;
    __syncthreads();
    for (int off = 64; off > 0; off >>= 1) {
        if (tid < off) red[tid] += red[tid + off];
        __syncthreads();
    }
    float inv = 1.0f / red[0];
    __syncthreads();
    {
        int half = tid >> 6;
        int d = tid & 63;
        float acc = 0.0f;
        int t0 = half * (TT / 2);
        for (int t = t0; t < t0 + TT / 2; t++)
            acc = fmaf(sc[t], vb[(size_t)t * DD + d], acc);
        red[tid] = acc;
    }
    __syncthreads();
    if (tid < 64)
        out[((size_t)n * TT) * HIDD + h * DD + tid] =
            (red[tid] + red[tid + 64]) * inv;
}

// ---------------- launch ----------------------------------------------------------
extern "C" void kernel_launch(void* const* d_in, const int* in_sizes, int n_in,
                              void* d_out, int out_size)
{
    (void)in_sizes; (void)n_in; (void)out_size;
    const float* hs   = (const float*)d_in[0];
    const float* mask = (const float*)d_in[1];
    const float* Wq   = (const float*)d_in[2];
    const float* bq   = (const float*)d_in[3];
    const float* Wk   = (const float*)d_in[4];
    const float* bk   = (const float*)d_in[5];
    const float* Wv   = (const float*)d_in[6];
    const float* bv   = (const float*)d_in[7];
    float* out = (float*)d_out;

    float *qp, *kp, *ktfp, *vp;
    cudaGetSymbolAddress((void**)&qp, g_q);
    cudaGetSymbolAddress((void**)&kp, g_k);
    cudaGetSymbolAddress((void**)&ktfp, g_ktf);
    cudaGetSymbolAddress((void**)&vp, g_v);
    uint2 *afh, *afl, *wfh, *wfl;
    cudaGetSymbolAddress((void**)&afh, g_Afh4);
    cudaGetSymbolAddress((void**)&afl, g_Afl4);
    cudaGetSymbolAddress((void**)&wfh, g_Wfh4);
    cudaGetSymbolAddress((void**)&wfl, g_Wfl4);

    {
        int n4a = NB * TT * HIDD / 4;
        cvt_a_kernel<<<(n4a + 255) / 256, 256>>>(hs, afh, afl, n4a);
        int n4w = HIDD * HIDD / 4;
        cvt_w_kernel<<<dim3((n4w + 255) / 256, 3), 256>>>(Wq, Wk, Wv, wfh, wfl, n4w);
        q0_kernel<<<dim3(HIDD, NB), 128>>>(hs, Wq, bq);
    }

    {
        cudaFuncSetAttribute(gemm_all_kernel,
                             cudaFuncAttributeMaxDynamicSharedMemorySize, GSMEMB);
        gemm_all_kernel<<<dim3(HIDD / 128, (NB * TT) / 128, 3), 256, GSMEMB>>>(
            bq, bk, bv, qp, kp, ktfp, vp);
    }

    select_kernel<<<dim3(TT / 256, NHH, NB), 256>>>(mask, bq);

    size_t lsmem = (size_t)LSMEM_WORDS * sizeof(float);
    cudaFuncSetAttribute(attn_fused_kernel,
                         cudaFuncAttributeMaxDynamicSharedMemorySize, (int)lsmem);
    attn_fused_kernel<<<dim3(TT / 128, NHH, NB), 256, lsmem>>>(mask, out);

    bos_kernel<<<dim3(NHH, NB), 128>>>(mask, out);
}

// round 16
// speedup vs baseline: 1.1017x; 1.0516x over previous
#include <cuda_runtime.h>
#include <cuda_bf16.h>
#include <cuda_fp16.h>
#include <math.h>

#define NB   2
#define TT   4096
#define HIDD 1024
#define NHH  16
#define DD   64
#define TOPKK 16
#define NEGV (-10000.0f)

// ---------------- device scratch ----------------
__device__ float g_k[(size_t)NB*NHH*TT*DD];     // exact (selection, bos)
__device__ float g_v[(size_t)NB*NHH*TT*DD];     // tf32-rounded (attn PV, bos)
__device__ float g_q0[(size_t)NB*HIDD];
__device__ int   g_gidx[(size_t)NB*NHH*(TT/4)];
__device__ int   g_lidx[(size_t)NB*NHH*(3*TT/4)];
__device__ uint4 g_q16[(size_t)NB*NHH*TT*DD/8];   // fp16 Q (attn S)
__device__ uint4 g_k16[(size_t)NB*NHH*TT*DD/8];   // fp16 K (attn S)
__device__ uint4 g_Afh4[(size_t)NB*TT*HIDD/8];
__device__ uint4 g_Afl4[(size_t)NB*TT*HIDD/8];
__device__ uint4 g_Wfh4[(size_t)3*HIDD*HIDD/8];   // 0=Wq, 1=Wv, 2=Wk
__device__ uint4 g_Wfl4[(size_t)HIDD*HIDD/8];     // Wk lo

// ---------------- helpers ----------------
__device__ __forceinline__ void mma_f16(float& d0, float& d1, float& d2, float& d3,
                                        unsigned a0, unsigned a1, unsigned a2, unsigned a3,
                                        unsigned b0, unsigned b1)
{
    asm("mma.sync.aligned.m16n8k16.row.col.f32.f16.f16.f32 "
        "{%0,%1,%2,%3}, {%4,%5,%6,%7}, {%8,%9}, {%0,%1,%2,%3};\n"
        : "+f"(d0), "+f"(d1), "+f"(d2), "+f"(d3)
        : "r"(a0), "r"(a1), "r"(a2), "r"(a3), "r"(b0), "r"(b1));
}

__device__ __forceinline__ void ldsm4(unsigned& r0, unsigned& r1,
                                      unsigned& r2, unsigned& r3, unsigned saddr)
{
    asm volatile("ldmatrix.sync.aligned.m8n8.x4.shared.b16 {%0,%1,%2,%3}, [%4];"
                 : "=r"(r0), "=r"(r1), "=r"(r2), "=r"(r3) : "r"(saddr));
}

__device__ __forceinline__ void cp16(void* smem_dst, const void* gsrc)
{
    unsigned saddr = (unsigned)__cvta_generic_to_shared(smem_dst);
    asm volatile("cp.async.ca.shared.global [%0], [%1], 16;\n"
                 :: "r"(saddr), "l"(gsrc));
}
__device__ __forceinline__ void cp8(void* smem_dst, const void* gsrc)
{
    unsigned saddr = (unsigned)__cvta_generic_to_shared(smem_dst);
    asm volatile("cp.async.ca.shared.global [%0], [%1], 8;\n"
                 :: "r"(saddr), "l"(gsrc));
}
__device__ __forceinline__ void cp_commit()
{
    asm volatile("cp.async.commit_group;\n" ::: "memory");
}
template <int N> __device__ __forceinline__ void cp_wait()
{
    asm volatile("cp.async.wait_group %0;\n" :: "n"(N) : "memory");
}

__device__ __forceinline__ float to_tf32(float x)
{
    float r;
    asm("cvt.rna.tf32.f32 %0, %1;" : "=f"(r) : "f"(x));
    return r;
}

__device__ __forceinline__ void mma_tf32(float& d0, float& d1, float& d2, float& d3,
                                         float a0, float a1, float a2, float a3,
                                         float b0, float b1)
{
    asm("mma.sync.aligned.m16n8k8.row.col.f32.tf32.tf32.f32 "
        "{%0,%1,%2,%3}, {%4,%5,%6,%7}, {%8,%9}, {%0,%1,%2,%3};\n"
        : "+f"(d0), "+f"(d1), "+f"(d2), "+f"(d3)
        : "r"(__float_as_uint(a0)), "r"(__float_as_uint(a1)),
          "r"(__float_as_uint(a2)), "r"(__float_as_uint(a3)),
          "r"(__float_as_uint(b0)), "r"(__float_as_uint(b1)));
}

__device__ __forceinline__ unsigned pack_h2(float v0, float v1)
{
    return (unsigned)__half_as_ushort(__float2half_rn(v0)) |
           ((unsigned)__half_as_ushort(__float2half_rn(v1)) << 16);
}

// ---------------- conversions ------------------------------------------------------
__device__ __forceinline__ uint2 pack_hi4(float4 v)
{
    __half h0 = __float2half_rn(v.x), h1 = __float2half_rn(v.y);
    __half h2 = __float2half_rn(v.z), h3 = __float2half_rn(v.w);
    return make_uint2((unsigned)__half_as_ushort(h0) | ((unsigned)__half_as_ushort(h1) << 16),
                      (unsigned)__half_as_ushort(h2) | ((unsigned)__half_as_ushort(h3) << 16));
}
__device__ __forceinline__ uint2 pack_lo4(float4 v)
{
    __half h0 = __float2half_rn(v.x), h1 = __float2half_rn(v.y);
    __half h2 = __float2half_rn(v.z), h3 = __float2half_rn(v.w);
    __half l0 = __float2half_rn(v.x - __half2float(h0));
    __half l1 = __float2half_rn(v.y - __half2float(h1));
    __half l2 = __float2half_rn(v.z - __half2float(h2));
    __half l3 = __float2half_rn(v.w - __half2float(h3));
    return make_uint2((unsigned)__half_as_ushort(l0) | ((unsigned)__half_as_ushort(l1) << 16),
                      (unsigned)__half_as_ushort(l2) | ((unsigned)__half_as_ushort(l3) << 16));
}

__global__ void cvt_a_kernel(const float* __restrict__ in,
                             uint2* __restrict__ fh, uint2* __restrict__ fl, int n4)
{
    int i = blockIdx.x * blockDim.x + threadIdx.x;
    if (i >= n4) return;
    float4 v = ((const float4*)in)[i];
    fh[i] = pack_hi4(v);
    fl[i] = pack_lo4(v);
}

__global__ void cvt_w_kernel(const float* __restrict__ Wq,
                             const float* __restrict__ Wk,
                             const float* __restrict__ Wv,
                             uint2* __restrict__ fh, uint2* __restrict__ fl, int n4)
{
    int i = blockIdx.x * blockDim.x + threadIdx.x;
    if (i >= n4) return;
    int w = blockIdx.y;
    const float* in = (w == 0) ? Wq : (w == 1) ? Wk : Wv;
    int slot = (w == 0) ? 0 : (w == 1) ? 2 : 1;
    float4 v = ((const float4*)in)[i];
    fh[(size_t)slot * n4 + i] = pack_hi4(v);
    if (w == 1) fl[i] = pack_lo4(v);
}

__global__ void q0_kernel(const float* __restrict__ hs,
                          const float* __restrict__ Wq,
                          const float* __restrict__ bq)
{
    const int c = blockIdx.x;
    const int n = blockIdx.y;
    const int tid = threadIdx.x;
    __shared__ float red[128];
    const float* xr = hs + (size_t)n * TT * HIDD;
    const float* wr = Wq + (size_t)c * HIDD;
    float pa = 0.0f;
    for (int k = tid; k < HIDD; k += 128) pa = fmaf(xr[k], wr[k], pa);
    red[tid] = pa;
    __syncthreads();
    for (int off = 64; off > 0; off >>= 1) {
        if (tid < off) red[tid] += red[tid + off];
        __syncthreads();
    }
    if (tid == 0) g_q0[(size_t)n * HIDD + c] = red[0] + bq[c];
}

// ============= fused QKV GEMM: per-output term counts =============================
// z=0 Q: 1 term -> fp16 out. z=1 V: 2 terms -> tf32 out. z=2 K: 3 terms -> fp32 + fp16.
#define KSTR 16
#define PLW  (128 * KSTR)
#define PA_HI 0
#define PA_LO (1 * PLW)
#define PB_HI (2 * PLW)
#define PB_LO (3 * PLW)
#define STGW  (4 * PLW)
#define GSMEMB (3 * STGW * 4)          /* 96KB */

__global__ __launch_bounds__(256, 2)
void gemm_all_kernel(const float* __restrict__ bq,
                     const float* __restrict__ bk,
                     const float* __restrict__ bv,
                     __half* __restrict__ oq16,
                     float* __restrict__ ok,
                     __half* __restrict__ ok16,
                     float* __restrict__ ov)
{
    extern __shared__ unsigned gsm[];
    const int tid = threadIdx.x;
    const int m0 = blockIdx.y * 128;
    const int n0 = blockIdx.x * 128;
    const int z  = blockIdx.z;
    const bool isK = (z == 2);
    const bool useALo = (z != 0);

    const char* Ah = (const char*)((const __half*)g_Afh4 + (size_t)m0 * HIDD);
    const char* Al = (const char*)((const __half*)g_Afl4 + (size_t)m0 * HIDD);
    const char* Bh = (const char*)((const __half*)g_Wfh4 + ((size_t)z * HIDD + n0) * HIDD);
    const char* Bl = (const char*)((const __half*)g_Wfl4 + (size_t)n0 * HIDD);
    const float* bias = (z == 0) ? bq : (z == 1) ? bv : bk;

    const int lane = tid & 31;
    const int warp = tid >> 5;
    const int wm = warp >> 1;
    const int wn = warp & 1;
    const int qr = lane >> 2;
    const int qc = lane & 3;
    const int rA = wm * 32;
    const int cB = wn * 64;

    const unsigned smem_base = (unsigned)__cvta_generic_to_shared(gsm);
    const int a_r0 = rA + (lane & 7) + ((lane >> 3) & 1) * 8;
    const unsigned a_kbit = (lane >> 4) & 1;
    const int b_r0 = cB + (lane & 7) + ((lane >> 4) & 1) * 8;
    const unsigned b_kbit = (lane >> 3) & 1;

    float acc[2][8][4];
#pragma unroll
    for (int mt = 0; mt < 2; mt++)
#pragma unroll
        for (int nt = 0; nt < 8; nt++)
#pragma unroll
            for (int e = 0; e < 4; e++) acc[mt][nt][e] = 0.0f;

    auto load_stage = [&](int buf, int kofs) {
        unsigned* st = gsm + buf * STGW;
#pragma unroll
        for (int i = 0; i < 2; i++) {
            int c = tid + i * 256;
            int row = c >> 2;
            int cw = c & 3;
            size_t go = ((size_t)row * HIDD + kofs + cw * 8) * 2;
            int pw = (cw ^ ((row >> 1) & 3)) * 4;
            unsigned* sp = st + row * KSTR + pw;
            cp16(sp + PA_HI, Ah + go);
            if (useALo) cp16(sp + PA_LO, Al + go);
            cp16(sp + PB_HI, Bh + go);
            if (isK) cp16(sp + PB_LO, Bl + go);
        }
        cp_commit();
    };

    load_stage(0, 0);
    load_stage(1, 32);

    const int NIT = HIDD / 32;
    int cur = 0;
    for (int it = 0; it < NIT; it++) {
        if (it + 1 < NIT) cp_wait<1>(); else cp_wait<0>();
        __syncthreads();
        if (it + 2 < NIT) {
            int s2 = cur + 2; if (s2 >= 3) s2 -= 3;
            load_stage(s2, (it + 2) * 32);
        }

        const unsigned sb = smem_base + cur * (STGW * 4);
#pragma unroll
        for (int s = 0; s < 2; s++) {
            unsigned a_hi[2][4], a_lo[2][4];
#pragma unroll
            for (int mt = 0; mt < 2; mt++) {
                int row = a_r0 + mt * 16;
                unsigned kc = (unsigned)s * 2 + a_kbit;
                unsigned ao = (unsigned)row * 64 + ((kc ^ ((unsigned)(row >> 1) & 3u)) << 4);
                ldsm4(a_hi[mt][0], a_hi[mt][1], a_hi[mt][2], a_hi[mt][3],
                      sb + PA_HI * 4 + ao);
                if (useALo)
                    ldsm4(a_lo[mt][0], a_lo[mt][1], a_lo[mt][2], a_lo[mt][3],
                          sb + PA_LO * 4 + ao);
            }
#pragma unroll
            for (int ph = 0; ph < 2; ph++) {
                unsigned bh[2][4], bl[2][4];
#pragma unroll
                for (int pp = 0; pp < 2; pp++) {
                    int p = ph * 2 + pp;
                    int row = b_r0 + p * 16;
                    unsigned kc = (unsigned)s * 2 + b_kbit;
                    unsigned bo = (unsigned)row * 64 + ((kc ^ ((unsigned)(row >> 1) & 3u)) << 4);
                    ldsm4(bh[pp][0], bh[pp][1], bh[pp][2], bh[pp][3],
                          sb + PB_HI * 4 + bo);
                    if (isK)
                        ldsm4(bl[pp][0], bl[pp][1], bl[pp][2], bl[pp][3],
                              sb + PB_LO * 4 + bo);
                }
#pragma unroll
                for (int pp = 0; pp < 2; pp++) {
                    int p = ph * 2 + pp;
#pragma unroll
                    for (int mt = 0; mt < 2; mt++) {
                        float* c0 = acc[mt][2 * p];
                        float* c1 = acc[mt][2 * p + 1];
                        mma_f16(c0[0], c0[1], c0[2], c0[3],
                                a_hi[mt][0], a_hi[mt][1], a_hi[mt][2], a_hi[mt][3],
                                bh[pp][0], bh[pp][1]);
                        mma_f16(c1[0], c1[1], c1[2], c1[3],
                                a_hi[mt][0], a_hi[mt][1], a_hi[mt][2], a_hi[mt][3],
                                bh[pp][2], bh[pp][3]);
                    }
                }
                if (useALo) {
#pragma unroll
                    for (int pp = 0; pp < 2; pp++) {
                        int p = ph * 2 + pp;
#pragma unroll
                        for (int mt = 0; mt < 2; mt++) {
                            float* c0 = acc[mt][2 * p];
                            float* c1 = acc[mt][2 * p + 1];
                            mma_f16(c0[0], c0[1], c0[2], c0[3],
                                    a_lo[mt][0], a_lo[mt][1], a_lo[mt][2], a_lo[mt][3],
                                    bh[pp][0], bh[pp][1]);
                            mma_f16(c1[0], c1[1], c1[2], c1[3],
                                    a_lo[mt][0], a_lo[mt][1], a_lo[mt][2], a_lo[mt][3],
                                    bh[pp][2], bh[pp][3]);
                        }
                    }
                }
                if (isK) {
#pragma unroll
                    for (int pp = 0; pp < 2; pp++) {
                        int p = ph * 2 + pp;
#pragma unroll
                        for (int mt = 0; mt < 2; mt++) {
                            float* c0 = acc[mt][2 * p];
                            float* c1 = acc[mt][2 * p + 1];
                            mma_f16(c0[0], c0[1], c0[2], c0[3],
                                    a_hi[mt][0], a_hi[mt][1], a_hi[mt][2], a_hi[mt][3],
                                    bl[pp][0], bl[pp][1]);
                            mma_f16(c1[0], c1[1], c1[2], c1[3],
                                    a_hi[mt][0], a_hi[mt][1], a_hi[mt][2], a_hi[mt][3],
                                    bl[pp][2], bl[pp][3]);
                        }
                    }
                }
            }
        }
        cur = (cur + 1 == 3) ? 0 : cur + 1;
    }

#pragma unroll
    for (int mt = 0; mt < 2; mt++) {
#pragma unroll
        for (int nt = 0; nt < 8; nt++) {
#pragma unroll
            for (int half = 0; half < 2; half++) {
                int row = m0 + rA + mt * 16 + qr + half * 8;
                int nb  = row >> 12;
                int t   = row & (TT - 1);
                int col = n0 + cB + nt * 8 + qc * 2;
                int h = col >> 6;
                int d = col & 63;
                size_t off = (((size_t)(nb * NHH + h)) * TT + t) * DD + d;
                float v0 = acc[mt][nt][half * 2 + 0] + bias[col];
                float v1 = acc[mt][nt][half * 2 + 1] + bias[col + 1];
                if (isK) {
                    ok[off] = v0; ok[off + 1] = v1;
                    *(unsigned*)(ok16 + off) = pack_h2(v0, v1);
                } else if (z == 0) {
                    *(unsigned*)(oq16 + off) = pack_h2(v0, v1);
                } else {
                    ov[off] = to_tf32(v0); ov[off + 1] = to_tf32(v1);
                }
            }
        }
    }
}

// ---------------- top-k selection (exact g_k) -------------------------------------
__global__ void select_kernel(const float* __restrict__ mask,
                              const float* __restrict__ bq)
{
    const int sub = threadIdx.x >> 6;
    const int i   = threadIdx.x & 63;
    const int blk = blockIdx.x * 4 + sub;
    const int h   = blockIdx.y;
    const int n   = blockIdx.z;
    __shared__ float norms[4][64];
    __shared__ int flags[4][64];

    const int token = blk * 64 + i;
    const float* kr = g_k + (((size_t)(n * NHH + h)) * TT + token) * DD;
    const float* bqr = bq + h * DD;
    float s = 0.0f;
#pragma unroll
    for (int d = 0; d < DD; d++) { float vv = kr[d] + bqr[d]; s += vv * vv; }
    if (mask[n * TT + token] != 0.0f) s = 0.0f;
    norms[sub][i] = s;
    __syncthreads();

    float mine = norms[sub][i];
    int rank = 0;
    for (int j = 0; j < 64; j++) {
        float nj = norms[sub][j];
        rank += (nj < mine) || (nj == mine && j < i);
    }
    int top = (rank >= 64 - TOPKK) ? 1 : 0;
    flags[sub][i] = top;
    __syncthreads();

    int pos = 0;
    for (int j = 0; j < i; j++) pos += flags[sub][j];
    if (top)
        g_gidx[((size_t)(n * NHH + h)) * (TT / 4) + blk * TOPKK + pos] = token;
    else
        g_lidx[((size_t)(n * NHH + h)) * (3 * TT / 4) + blk * 48 + (i - pos)] = token;
}

// ======== fused local+global flash: fp16 S, tf32 PV ================================
#define KC     112
#define NCH    4
#define QSH    72                      /* fp16 Q/K row stride (halves); 36 words */
#define VSTRW  72
// smem carve (float index base):
#define QH_OFF 0                       /* 128*72 halves = 4608 floats */
#define KH_OFF 4608                    /* 112*72 halves = 4032 floats */
#define VS_OFF (4608 + 4032)
#define MS_OFF (VS_OFF + KC*VSTRW)
#define LSMEM_WORDS (MS_OFF + KC)      /* 16816 floats = 67264 B */

template <int NT>
__device__ __forceinline__ void compute_S16(
    const __half* __restrict__ Qh, const __half* __restrict__ Kh,
    float (&s)[14][4], int rb, int w16, int qr, int qc)
{
#pragma unroll
    for (int nt = 0; nt < NT; nt++) {
        s[nt][0] = 0.f; s[nt][1] = 0.f; s[nt][2] = 0.f; s[nt][3] = 0.f;
    }
#pragma unroll
    for (int k16 = 0; k16 < 4; k16++) {
        const int ko = k16 * 16 + qc * 2;
        unsigned a0 = *(const unsigned*)(Qh + (w16 + qr) * QSH + ko);
        unsigned a1 = *(const unsigned*)(Qh + (w16 + qr + 8) * QSH + ko);
        unsigned a2 = *(const unsigned*)(Qh + (w16 + qr) * QSH + ko + 8);
        unsigned a3 = *(const unsigned*)(Qh + (w16 + qr + 8) * QSH + ko + 8);
#pragma unroll
        for (int nt = 0; nt < NT; nt++) {
            unsigned b0 = *(const unsigned*)(Kh + (rb + nt * 8 + qr) * QSH + ko);
            unsigned b1 = *(const unsigned*)(Kh + (rb + nt * 8 + qr) * QSH + ko + 8);
            mma_f16(s[nt][0], s[nt][1], s[nt][2], s[nt][3],
                    a0, a1, a2, a3, b0, b1);
        }
    }
}

template <int NT>
__device__ __forceinline__ void softmax_pv(
    const float* __restrict__ Vs, const float* __restrict__ Ms,
    float (&s)[14][4], int rb, int w16, int qr, int qc,
    int src0, int src2, bool odd,
    float& m0, float& m1, float& l0, float& l1, float (&o)[8][4])
{
    float cmax0 = -1e30f, cmax1 = -1e30f;
#pragma unroll
    for (int nt = 0; nt < NT; nt++) {
        float mc0 = Ms[rb + nt * 8 + 2 * qc];
        float mc1 = Ms[rb + nt * 8 + 2 * qc + 1];
        s[nt][0] = s[nt][0] * 0.125f + mc0;
        s[nt][1] = s[nt][1] * 0.125f + mc1;
        s[nt][2] = s[nt][2] * 0.125f + mc0;
        s[nt][3] = s[nt][3] * 0.125f + mc1;
        cmax0 = fmaxf(cmax0, fmaxf(s[nt][0], s[nt][1]));
        cmax1 = fmaxf(cmax1, fmaxf(s[nt][2], s[nt][3]));
    }
    cmax0 = fmaxf(cmax0, __shfl_xor_sync(0xffffffffu, cmax0, 1));
    cmax0 = fmaxf(cmax0, __shfl_xor_sync(0xffffffffu, cmax0, 2));
    cmax1 = fmaxf(cmax1, __shfl_xor_sync(0xffffffffu, cmax1, 1));
    cmax1 = fmaxf(cmax1, __shfl_xor_sync(0xffffffffu, cmax1, 2));

    float mn0 = fmaxf(m0, cmax0);
    float mn1 = fmaxf(m1, cmax1);
    float corr0 = __expf(m0 - mn0);
    float corr1 = __expf(m1 - mn1);
    m0 = mn0; m1 = mn1;

    float rs0 = 0.0f, rs1 = 0.0f;
#pragma unroll
    for (int nt = 0; nt < NT; nt++) {
        float p0 = __expf(s[nt][0] - mn0);
        float p1 = __expf(s[nt][1] - mn0);
        float p2 = __expf(s[nt][2] - mn1);
        float p3 = __expf(s[nt][3] - mn1);
        rs0 += p0 + p1; rs1 += p2 + p3;
        s[nt][0] = to_tf32(p0); s[nt][1] = to_tf32(p1);
        s[nt][2] = to_tf32(p2); s[nt][3] = to_tf32(p3);
    }
    rs0 += __shfl_xor_sync(0xffffffffu, rs0, 1);
    rs0 += __shfl_xor_sync(0xffffffffu, rs0, 2);
    rs1 += __shfl_xor_sync(0xffffffffu, rs1, 1);
    rs1 += __shfl_xor_sync(0xffffffffu, rs1, 2);
    l0 = l0 * corr0 + rs0;
    l1 = l1 * corr1 + rs1;

#pragma unroll
    for (int nt = 0; nt < 8; nt++) {
        o[nt][0] *= corr0; o[nt][1] *= corr0;
        o[nt][2] *= corr1; o[nt][3] *= corr1;
    }

#pragma unroll
    for (int kt = 0; kt < NT; kt++) {
        float p0 = s[kt][0], p1 = s[kt][1], p2 = s[kt][2], p3 = s[kt][3];
        float t0 = __shfl_sync(0xffffffffu, p0, src0);
        float t1 = __shfl_sync(0xffffffffu, p1, src0);
        float t2 = __shfl_sync(0xffffffffu, p2, src0);
        float t3 = __shfl_sync(0xffffffffu, p3, src0);
        float u0 = __shfl_sync(0xffffffffu, p0, src2);
        float u1 = __shfl_sync(0xffffffffu, p1, src2);
        float u2 = __shfl_sync(0xffffffffu, p2, src2);
        float u3 = __shfl_sync(0xffffffffu, p3, src2);
        float a0 = odd ? t1 : t0;
        float a1 = odd ? t3 : t2;
        float a2 = odd ? u1 : u0;
        float a3 = odd ? u3 : u2;
#pragma unroll
        for (int nt = 0; nt < 8; nt++) {
            float b0 = Vs[(rb + kt * 8 + qc) * VSTRW + nt * 8 + qr];
            float b1 = Vs[(rb + kt * 8 + qc + 4) * VSTRW + nt * 8 + qr];
            mma_tf32(o[nt][0], o[nt][1], o[nt][2], o[nt][3],
                     a0, a1, a2, a3, b0, b1);
        }
    }
}

__device__ __forceinline__ void calc_local(int ch, int qb, const int* __restrict__ lix,
                                           const float* __restrict__ mask_n,
                                           int tid, int (&tok)[7], float (&mv)[7])
{
    int r = tid >> 4;
#pragma unroll
    for (int i = 0; i < 7; i++) {
        int kk = ch * KC + r;
        if (kk < 288) {
            int g = qb * 96 - 96 + kk;
            if (g >= 0 && g < 3 * TT / 4) { tok[i] = lix[g]; mv[i] = mask_n[tok[i]]; }
            else { tok[i] = -1; mv[i] = NEGV; }
        } else if (kk == 288) {
            tok[i] = 0; mv[i] = 0.0f;
        } else {
            tok[i] = -1; mv[i] = NEGV;
        }
        r += 16;
    }
}

__device__ __forceinline__ void calc_global(int qb, const int* __restrict__ gix,
                                            const float* __restrict__ mask_n,
                                            int tid, int (&tok)[7], float (&mv)[7])
{
    int r = tid >> 4;
#pragma unroll
    for (int i = 0; i < 7; i++) {
        if (r < 96) {
            int half = (r >= 48) ? 1 : 0;
            int g = (2 * qb - 1 + half) * 16 + (r - half * 48);
            if (g >= 0 && g < TT / 4) { tok[i] = gix[g]; mv[i] = mask_n[tok[i]]; }
            else { tok[i] = -1; mv[i] = NEGV; }
        } else {
            tok[i] = -2;
        }
        r += 16;
    }
}

// K gather: fp16 rows, 16 threads/row, 8B per thread (cp.async size 8)
__device__ __forceinline__ void issue_K(__half* __restrict__ Kh,
                                        const __half* __restrict__ kb16,
                                        const int (&tok)[7], int tid)
{
    int r = tid >> 4;
    int c4 = tid & 15;
#pragma unroll
    for (int i = 0; i < 7; i++) {
        __half* dst = Kh + r * QSH + c4 * 4;
        if (tok[i] >= 0) cp8(dst, kb16 + (size_t)tok[i] * DD + c4 * 4);
        else if (tok[i] == -1) *(uint2*)dst = make_uint2(0u, 0u);
        r += 16;
    }
    cp_commit();
}

__device__ __forceinline__ void issue_V(float* __restrict__ Vs, float* __restrict__ Ms,
                                        const float* __restrict__ vb,
                                        const int (&tok)[7], const float (&mv)[7], int tid)
{
    int r = tid >> 4;
    int c4 = tid & 15;
#pragma unroll
    for (int i = 0; i < 7; i++) {
        float* dst = Vs + r * VSTRW + c4 * 4;
        if (tok[i] >= 0) cp16(dst, vb + (size_t)tok[i] * DD + c4 * 4);
        else if (tok[i] == -1) *(float4*)dst = make_float4(0.f, 0.f, 0.f, 0.f);
        if (tok[i] != -2 && c4 == 0) Ms[r] = mv[i];
        r += 16;
    }
    cp_commit();
}

__global__ __launch_bounds__(256, 2)
void attn_fused_kernel(const float* __restrict__ mask,
                       float* __restrict__ out)
{
    extern __shared__ float sm[];
    __half* Qh = (__half*)(sm + QH_OFF);
    __half* Kh = (__half*)(sm + KH_OFF);
    float* Vs = sm + VS_OFF;
    float* Ms = sm + MS_OFF;

    const int qb = blockIdx.x;
    const int h  = blockIdx.y;
    const int n  = blockIdx.z;
    const int tid = threadIdx.x;
    const int lane = tid & 31;
    const int warp = tid >> 5;
    const int qr = lane >> 2;
    const int qc = lane & 3;
    const int w16 = warp * 16;

    const size_t ho = (size_t)(n * NHH + h);
    const __half* kb16 = (const __half*)g_k16 + ho * TT * DD;
    const __half* qb16 = (const __half*)g_q16 + ho * TT * DD;
    const float* vb = g_v + ho * TT * DD;
    const int* lix = g_lidx + ho * (3 * TT / 4);
    const int* gix = g_gidx + ho * (TT / 4);
    const float* mask_n = mask + (size_t)n * TT;

    // load Q tile (fp16, 8B chunks: 128 rows x 16 chunks)
#pragma unroll
    for (int i = 0; i < 8; i++) {
        int idx = tid + i * 256;
        int r = idx >> 4, c = idx & 15;
        *(uint2*)(Qh + r * QSH + c * 4) =
            *(const uint2*)(qb16 + (size_t)(qb * 128 + r) * DD + c * 4);
    }

    int tok[7];
    float mv[7];
    calc_local(0, qb, lix, mask_n, tid, tok, mv);
    issue_K(Kh, kb16, tok, tid);
    issue_V(Vs, Ms, vb, tok, mv, tid);

    float m0 = -1e30f, m1 = -1e30f, l0 = 0.0f, l1 = 0.0f;
    float o[8][4];
#pragma unroll
    for (int nt = 0; nt < 8; nt++)
#pragma unroll
        for (int e = 0; e < 4; e++) o[nt][e] = 0.0f;

    const int src0 = (qr << 2) + (qc >> 1);
    const int src2 = src0 + 2;
    const bool odd = (qc & 1) != 0;

    float s[14][4];

    for (int ch = 0; ch < NCH; ch++) {
        const bool glob = (ch == NCH - 1);
        cp_wait<1>();
        __syncthreads();

        int rb = 0;
        if (!glob) {
            compute_S16<14>(Qh, Kh, s, 0, w16, qr, qc);
        } else {
            rb = (warp >= 4) ? 48 : 0;
            compute_S16<6>(Qh, Kh, s, rb, w16, qr, qc);
        }
        __syncthreads();

        if (ch + 1 < NCH) {
            if (ch + 1 == NCH - 1) calc_global(qb, gix, mask_n, tid, tok, mv);
            else                   calc_local(ch + 1, qb, lix, mask_n, tid, tok, mv);
            issue_K(Kh, kb16, tok, tid);
            cp_wait<1>();
        } else {
            cp_wait<0>();
        }
        __syncthreads();

        if (!glob)
            softmax_pv<14>(Vs, Ms, s, 0, w16, qr, qc, src0, src2, odd,
                           m0, m1, l0, l1, o);
        else
            softmax_pv<6>(Vs, Ms, s, rb, w16, qr, qc, src0, src2, odd,
                          m0, m1, l0, l1, o);
        __syncthreads();

        if (ch + 1 < NCH)
            issue_V(Vs, Ms, vb, tok, mv, tid);
    }

    float inv0 = 1.0f / l0;
    float inv1 = 1.0f / l1;
    int row0 = qb * 128 + w16 + qr;
    int row1 = row0 + 8;
    float* op0 = out + ((size_t)n * TT + row0) * HIDD + h * DD;
    float* op1 = out + ((size_t)n * TT + row1) * HIDD + h * DD;
#pragma unroll
    for (int nt = 0; nt < 8; nt++) {
        int c0 = nt * 8 + 2 * qc;
#pragma unroll
        for (int e = 0; e < 2; e++) {
            op0[c0 + e] = o[nt][e] * inv0;
            op1[c0 + e] = o[nt][2 + e] * inv1;
        }
    }
}

// ---------------- BOS row ----------------------------------------------------------
__global__ void bos_kernel(const float* __restrict__ mask,
                           float* __restrict__ out)
{
    const int h = blockIdx.x;
    const int n = blockIdx.y;
    const int tid = threadIdx.x;
    __shared__ float sc[TT];
    __shared__ float qs[64];
    __shared__ float red[128];

    const size_t ho = (size_t)(n * NHH + h);
    const float* kb = g_k + ho * TT * DD;
    const float* vb = g_v + ho * TT * DD;
    if (tid < 64) qs[tid] = g_q0[(size_t)n * HIDD + h * DD + tid];
    __syncthreads();

    float lmax = -1e30f;
    for (int t = tid; t < TT; t += 128) {
        const float* kr = kb + (size_t)t * DD;
        float dot = 0.0f;
#pragma unroll
        for (int d = 0; d < 64; d++) dot = fmaf(qs[d], kr[d], dot);
        float s = dot + mask[n * TT + t];
        sc[t] = s;
        lmax = fmaxf(lmax, s);
    }
    red[tid] = lmax;
    __syncthreads();
    for (int off = 64; off > 0; off >>= 1) {
        if (tid < off) red[tid] = fmaxf(red[tid], red[tid + off]);
        __syncthreads();
    }
    float mmax = red[0];
    float lsum = 0.0f;
    for (int t = tid; t < TT; t += 128) {
        float p = __expf(sc[t] - mmax);
        sc[t] = p;
        lsum += p;
    }
    __syncthreads();
    red[tid] = lsum;
    __syncthreads();
    for (int off = 64; off > 0; off >>= 1) {
        if (tid < off) red[tid] += red[tid + off];
        __syncthreads();
    }
    float inv = 1.0f / red[0];
    __syncthreads();
    {
        int half = tid >> 6;
        int d = tid & 63;
        float acc = 0.0f;
        int t0 = half * (TT / 2);
        for (int t = t0; t < t0 + TT / 2; t++)
            acc = fmaf(sc[t], vb[(size_t)t * DD + d], acc);
        red[tid] = acc;
    }
    __syncthreads();
    if (tid < 64)
        out[((size_t)n * TT) * HIDD + h * DD + tid] =
            (red[tid] + red[tid + 64]) * inv;
}

// ---------------- launch ----------------------------------------------------------
extern "C" void kernel_launch(void* const* d_in, const int* in_sizes, int n_in,
                              void* d_out, int out_size)
{
    (void)in_sizes; (void)n_in; (void)out_size;
    const float* hs   = (const float*)d_in[0];
    const float* mask = (const float*)d_in[1];
    const float* Wq   = (const float*)d_in[2];
    const float* bq   = (const float*)d_in[3];
    const float* Wk   = (const float*)d_in[4];
    const float* bk   = (const float*)d_in[5];
    const float* Wv   = (const float*)d_in[6];
    const float* bv   = (const float*)d_in[7];
    float* out = (float*)d_out;

    float *kp, *vp;
    __half *q16p, *k16p;
    cudaGetSymbolAddress((void**)&kp, g_k);
    cudaGetSymbolAddress((void**)&vp, g_v);
    cudaGetSymbolAddress((void**)&q16p, g_q16);
    cudaGetSymbolAddress((void**)&k16p, g_k16);
    uint2 *afh, *afl, *wfh, *wfl;
    cudaGetSymbolAddress((void**)&afh, g_Afh4);
    cudaGetSymbolAddress((void**)&afl, g_Afl4);
    cudaGetSymbolAddress((void**)&wfh, g_Wfh4);
    cudaGetSymbolAddress((void**)&wfl, g_Wfl4);

    {
        int n4a = NB * TT * HIDD / 4;
        cvt_a_kernel<<<(n4a + 255) / 256, 256>>>(hs, afh, afl, n4a);
        int n4w = HIDD * HIDD / 4;
        cvt_w_kernel<<<dim3((n4w + 255) / 256, 3), 256>>>(Wq, Wk, Wv, wfh, wfl, n4w);
        q0_kernel<<<dim3(HIDD, NB), 128>>>(hs, Wq, bq);
    }

    {
        cudaFuncSetAttribute(gemm_all_kernel,
                             cudaFuncAttributeMaxDynamicSharedMemorySize, GSMEMB);
        gemm_all_kernel<<<dim3(HIDD / 128, (NB * TT) / 128, 3), 256, GSMEMB>>>(
            bq, bk, bv, q16p, kp, k16p, vp);
    }

    select_kernel<<<dim3(TT / 256, NHH, NB), 256>>>(mask, bq);

    size_t lsmem = (size_t)LSMEM_WORDS * sizeof(float);   // ~67.3 KB
    cudaFuncSetAttribute(attn_fused_kernel,
                         cudaFuncAttributeMaxDynamicSharedMemorySize, (int)lsmem);
    attn_fused_kernel<<<dim3(TT / 128, NHH, NB), 256, lsmem>>>(mask, out);

    bos_kernel<<<dim3(NHH, NB), 128>>>(mask, out);
}